// round 6
// baseline (speedup 1.0000x reference)
#include <cuda_runtime.h>
#include <cstdint>

// ---------------------------------------------------------------------------
// GRU_2602750181500: bidirectional GRU, T=2048, B=32, F=H=512, fp32.
// Kernel 1: gi = x @ w_ih^T + b_ih (both dirs), fp32 FFMA2 GEMM.
// Kernel 2: persistent recurrence, 8 clusters x 16 CTAs.
//   R6: h exchanged via DSMEM scatter + per-CTA mbarriers (full: 1024 per-store
//   arrivals w/ release; empty: 16 read-done arrivals). No cluster barriers in
//   the loop (R4's mistake: ~380cyc + L1 flush each), no L2 flags, no fences,
//   no per-step 16KB L2 copy. GEMV identical to R5 (FFMA2-pipe floor).
// ---------------------------------------------------------------------------

#define T_ 2048
#define B_ 32
#define H_ 512
#define G_ 1536

typedef unsigned long long ull;

__device__ __forceinline__ ull pkf(float lo, float hi) {
    ull r; asm("mov.b64 %0, {%1, %2};" : "=l"(r) : "f"(lo), "f"(hi)); return r;
}
__device__ __forceinline__ void fma2(ull& d, ull a, ull b) {
    asm("fma.rn.f32x2 %0, %1, %2, %0;" : "+l"(d) : "l"(a), "l"(b));
}
__device__ __forceinline__ float2 upk(ull v) {
    float2 f; asm("mov.b64 {%0, %1}, %2;" : "=f"(f.x), "=f"(f.y) : "l"(v)); return f;
}

__device__ __forceinline__ uint32_t smem_u32(const void* p) {
    uint32_t a;
    asm("{ .reg .u64 t; cvta.to.shared.u64 t, %1; cvt.u32.u64 %0, t; }"
        : "=r"(a) : "l"(p));
    return a;
}
__device__ __forceinline__ uint32_t mapa_rank(uint32_t laddr, int rank) {
    uint32_t r;
    asm("mapa.shared::cluster.u32 %0, %1, %2;" : "=r"(r) : "r"(laddr), "r"(rank));
    return r;
}
__device__ __forceinline__ void st_dsmem_v4(uint32_t addr, float4 v) {
    asm volatile("st.shared::cluster.v4.b32 [%0], {%1, %2, %3, %4};"
                 :: "r"(addr), "f"(v.x), "f"(v.y), "f"(v.z), "f"(v.w) : "memory");
}
__device__ __forceinline__ void mbar_init(uint32_t addr, unsigned count) {
    asm volatile("mbarrier.init.shared.b64 [%0], %1;" :: "r"(addr), "r"(count) : "memory");
}
__device__ __forceinline__ void mbar_arrive_remote(uint32_t addr) {
    asm volatile("mbarrier.arrive.release.cluster.shared::cluster.b64 _, [%0];"
                 :: "r"(addr) : "memory");
}
__device__ __forceinline__ void mbar_wait_parity(uint32_t addr, unsigned parity) {
    unsigned done;
    asm volatile(
        "{\n\t.reg .pred p;\n\t"
        "mbarrier.try_wait.parity.acquire.cluster.shared::cta.b64 p, [%1], %2;\n\t"
        "selp.b32 %0, 1, 0, p;\n\t}"
        : "=r"(done) : "r"(addr), "r"(parity) : "memory");
    while (!done) {
        asm volatile(
            "{\n\t.reg .pred p;\n\t"
            "mbarrier.try_wait.parity.acquire.cluster.shared::cta.b64 p, [%1], %2, 0x989680;\n\t"
            "selp.b32 %0, 1, 0, p;\n\t}"
            : "=r"(done) : "r"(addr), "r"(parity) : "memory");
    }
}
#define CLUSTER_SYNC() do { \
    asm volatile("barrier.cluster.arrive.aligned;" ::: "memory"); \
    asm volatile("barrier.cluster.wait.aligned;"   ::: "memory"); \
} while (0)

// Scratch (device global: allocation-free rule).
__device__ float g_gi[2][(size_t)T_ * B_ * G_];   // [dir][t*B+b][3H]

// ---------------------------------------------------------------------------
// Kernel 1: gi GEMM (FFMA2, unchanged — ~82% of FFMA2 ceiling).
// ---------------------------------------------------------------------------
__global__ void __launch_bounds__(256, 2) gi_gemm(
    const float* __restrict__ x,
    const float* __restrict__ wf, const float* __restrict__ bf,
    const float* __restrict__ wr, const float* __restrict__ br)
{
    __shared__ float Xs[8][132];
    __shared__ float Ws[8][132];

    const int tid = threadIdx.x;
    const int dir = blockIdx.z;
    const float* __restrict__ w    = dir ? wr : wf;
    const float* __restrict__ bias = dir ? br : bf;
    float* __restrict__ gi = g_gi[dir];

    const int m0 = blockIdx.y * 128;
    const int n0 = blockIdx.x * 128;

    const int lr = tid >> 1;
    const int lc = (tid & 1) * 4;

    const float* xg = x + (size_t)(m0 + lr) * 512 + lc;
    const float* wg = w + (size_t)(n0 + lr) * 512 + lc;

    const int tx = tid & 15, ty = tid >> 4;

    ull acc[8][4];
#pragma unroll
    for (int i = 0; i < 8; i++)
#pragma unroll
        for (int j = 0; j < 4; j++) acc[i][j] = 0ULL;

    float4 xa = *(const float4*)xg;
    float4 wa = *(const float4*)wg;

    for (int kt = 0; kt < 512; kt += 8) {
        Xs[lc + 0][lr] = xa.x; Xs[lc + 1][lr] = xa.y;
        Xs[lc + 2][lr] = xa.z; Xs[lc + 3][lr] = xa.w;
        Ws[lc + 0][lr] = wa.x; Ws[lc + 1][lr] = wa.y;
        Ws[lc + 2][lr] = wa.z; Ws[lc + 3][lr] = wa.w;
        __syncthreads();
        if (kt + 8 < 512) {
            xa = *(const float4*)(xg + kt + 8);
            wa = *(const float4*)(wg + kt + 8);
        }
#pragma unroll
        for (int kk = 0; kk < 8; kk++) {
            float4 a0 = *(const float4*)&Xs[kk][ty * 8];
            float4 a1 = *(const float4*)&Xs[kk][ty * 8 + 4];
            float4 b0 = *(const float4*)&Ws[kk][tx * 8];
            float4 b1 = *(const float4*)&Ws[kk][tx * 8 + 4];
            ull bq[4] = { pkf(b0.x, b0.y), pkf(b0.z, b0.w),
                          pkf(b1.x, b1.y), pkf(b1.z, b1.w) };
            float av[8] = { a0.x, a0.y, a0.z, a0.w, a1.x, a1.y, a1.z, a1.w };
#pragma unroll
            for (int i = 0; i < 8; i++) {
                ull aq = pkf(av[i], av[i]);
#pragma unroll
                for (int j = 0; j < 4; j++) fma2(acc[i][j], aq, bq[j]);
            }
        }
        __syncthreads();
    }

    float bb2[8];
#pragma unroll
    for (int j = 0; j < 8; j++) bb2[j] = bias[n0 + tx * 8 + j];
#pragma unroll
    for (int i = 0; i < 8; i++) {
        float* cp = gi + (size_t)(m0 + ty * 8 + i) * G_ + n0 + tx * 8;
#pragma unroll
        for (int j = 0; j < 4; j++) {
            float2 v = upk(acc[i][j]);
            v.x += bb2[2 * j]; v.y += bb2[2 * j + 1];
            *(float2*)(cp + 2 * j) = v;
        }
    }
}

// ---------------------------------------------------------------------------
// Kernel 2: recurrence, 8 clusters x 16 CTAs, DSMEM + mbarrier exchange.
// SMEM (floats): [0:8) mbarriers | sw [96][513] | sh [512][8] | sgh [4][776]
//                | sst [256]
// ---------------------------------------------------------------------------
#define SW2      513
#define OFF_SW   8
#define OFF_H    (OFF_SW + 96 * SW2)     // 49256
#define OFF_GH   (OFF_H + 512 * 8)       // 53352
#define OFF_ST   (OFF_GH + 4 * 776)      // 56456
#define SMEM_TOT (OFF_ST + 256)          // 56712 floats = 226848 B
#define SMEM_REC (SMEM_TOT * 4)

__global__ void __launch_bounds__(256, 1) gru_rec(
    const float* __restrict__ h0,
    const float* __restrict__ whh_f, const float* __restrict__ bhh_f,
    const float* __restrict__ whh_r, const float* __restrict__ bhh_r,
    float* __restrict__ out, int out_size)
{
    extern __shared__ float smem[];
    float* sw  = smem + OFF_SW;     // [96 r][513]
    float* sh  = smem + OFF_H;      // [512 k][8 b]
    float* sgh = smem + OFF_GH;     // [4 khp][8 b][97]
    float* sst = smem + OFF_ST;     // [256] hn staging (chunk layout)

    const uint32_t bar_base   = smem_u32(smem);
    const uint32_t full_addr  = bar_base;        // 8B
    const uint32_t empty_addr = bar_base + 8;    // 8B

    const int tid  = threadIdx.x;
    const int warp = tid >> 5;
    const int lane = tid & 31;
    const int bid = blockIdx.x;
    const int dir = bid >> 6;
    const int bg  = (bid >> 4) & 3;
    const int sl  = bid & 15;       // == cluster rank

    const float* __restrict__ whh = dir ? whh_r : whh_f;
    const float* __restrict__ bhh = dir ? bhh_r : bhh_f;
    const float* __restrict__ gi  = g_gi[dir];

    // mbarrier init: full = 1024 per-store arrivals, empty = 16 read-done.
    if (tid == 0) {
        mbar_init(full_addr, 1024);
        mbar_init(empty_addr, 16);
    }

    // Load 96 w_hh rows into SMEM (stride 513: conflict-free LDS.32).
    for (int idx = tid; idx < 96 * 128; idx += 256) {
        int r = idx >> 7, c4 = (idx & 127) << 2;
        int gate = r >> 5, il2 = r & 31;
        float4 v = *(const float4*)&whh[(size_t)((gate << 9) + sl * 32 + il2) * 512 + c4];
        float* d = &sw[r * SW2 + c4];
        d[0] = v.x; d[1] = v.y; d[2] = v.z; d[3] = v.w;
    }

    // Local init of full h(0).
    for (int i = tid; i < 4096; i += 256) {
        int k = i >> 3, b2 = i & 7;
        sh[i] = h0[(size_t)(dir * B_ + bg * 8 + b2) * H_ + k];
    }

    const int il = lane;
    const int iglob = sl * 32 + il;
    const int bglob = bg * 8 + warp;

    float hold = h0[(size_t)(dir * B_ + bglob) * H_ + iglob];

    const float bh_r = bhh[iglob];
    const float bh_z = bhh[512 + iglob];
    const float bh_n = bhh[1024 + iglob];

    // Scatter targets: thread t sends 4 float4s of this CTA's 1KB chunk,
    // each to a different rank; chunk slot in every peer = [sl*256, sl*256+256).
    const uint32_t sh_addr = smem_u32(sh);
    uint32_t raddr[4], rfull[4];
    int      soff[4];
#pragma unroll
    for (int i = 0; i < 4; i++) {
        int g = tid + 256 * i;          // 0..1023
        int rank = g >> 6;              // 0..15
        soff[i]  = (g & 63) * 4;
        raddr[i] = mapa_rank(sh_addr + (uint32_t)(sl * 256 + soff[i]) * 4u, rank);
        rfull[i] = mapa_rank(full_addr, rank);
    }
    const uint32_t rempty = (tid < 16) ? mapa_rank(empty_addr, tid) : 0u;

    __syncthreads();
    CLUSTER_SYNC();                     // barriers init'd + h(0) local everywhere

    const bool write_states = (out_size > T_ * B_ * 2 * H_);

    // GEMV pointers: warp = k-chunk (64 k), lane = base row (3 rows/thread).
    const float* wp0 = sw + lane * SW2 + warp * 64;
    const float* wp1 = wp0 + 32 * SW2;
    const float* wp2 = wp0 + 64 * SW2;

    for (int s = 0; s < T_; s++) {
        const int xrow = dir ? (T_ - 1 - s) : s;

        // gi loads issued before the wait (latency hidden under wait+GEMV).
        const float* gp = gi + ((size_t)xrow * B_ + bglob) * G_ + iglob;
        const float gir = __ldcs(gp);
        const float giz = __ldcs(gp + 512);
        const float gin = __ldcs(gp + 1024);

        // h(s) ready? (phase s-1 of full barrier; h(0) was loaded locally)
        if (s > 0) mbar_wait_parity(full_addr, (unsigned)(s - 1) & 1u);

        // GEMV: 3 rows x 8 batches x 64 k per thread.
        ull a0[4], a1[4], a2[4];
#pragma unroll
        for (int j = 0; j < 4; j++) { a0[j] = 0; a1[j] = 0; a2[j] = 0; }

        const ull* hp = (const ull*)sh + (size_t)warp * 64 * 4;
#pragma unroll 4
        for (int kk = 0; kk < 64; kk++) {
            const float w0 = wp0[kk];
            const float w1 = wp1[kk];
            const float w2 = wp2[kk];
            ulonglong2 hA = *(const ulonglong2*)(hp + (size_t)kk * 4);
            ulonglong2 hB = *(const ulonglong2*)(hp + (size_t)kk * 4 + 2);
            const ull q0 = pkf(w0, w0);
            fma2(a0[0], q0, hA.x); fma2(a0[1], q0, hA.y);
            fma2(a0[2], q0, hB.x); fma2(a0[3], q0, hB.y);
            const ull q1 = pkf(w1, w1);
            fma2(a1[0], q1, hA.x); fma2(a1[1], q1, hA.y);
            fma2(a1[2], q1, hB.x); fma2(a1[3], q1, hB.y);
            const ull q2 = pkf(w2, w2);
            fma2(a2[0], q2, hA.x); fma2(a2[1], q2, hA.y);
            fma2(a2[2], q2, hB.x); fma2(a2[3], q2, hB.y);
        }
        __syncthreads();                // all reads of sh (h(s)) complete

        // Tell peers my sh may be overwritten (fire before reduction so
        // peers' scatters overlap my epilogue). Anti-dependency only.
        if (s < T_ - 1 && tid < 16) mbar_arrive_remote(rempty);

        // Reduction stage 1: warps 0-3 store partials ([khp][b][97]).
        float* sb = sgh + (warp & 3) * 776;
        if (warp < 4) {
#pragma unroll
            for (int j = 0; j < 4; j++) {
                float2 p;
                p = upk(a0[j]);
                sb[(2 * j) * 97 + lane]          = p.x;
                sb[(2 * j + 1) * 97 + lane]      = p.y;
                p = upk(a1[j]);
                sb[(2 * j) * 97 + 32 + lane]     = p.x;
                sb[(2 * j + 1) * 97 + 32 + lane] = p.y;
                p = upk(a2[j]);
                sb[(2 * j) * 97 + 64 + lane]     = p.x;
                sb[(2 * j + 1) * 97 + 64 + lane] = p.y;
            }
        }
        __syncthreads();
        // Stage 2: warps 4-7 add their partials.
        if (warp >= 4) {
#pragma unroll
            for (int j = 0; j < 4; j++) {
                float2 p;
                p = upk(a0[j]);
                sb[(2 * j) * 97 + lane]          += p.x;
                sb[(2 * j + 1) * 97 + lane]      += p.y;
                p = upk(a1[j]);
                sb[(2 * j) * 97 + 32 + lane]     += p.x;
                sb[(2 * j + 1) * 97 + 32 + lane] += p.y;
                p = upk(a2[j]);
                sb[(2 * j) * 97 + 64 + lane]     += p.x;
                sb[(2 * j + 1) * 97 + 64 + lane] += p.y;
            }
        }
        __syncthreads();

        // Epilogue: b = warp, il = lane.
        float ghr = bh_r, ghz = bh_z, ghn = bh_n;
#pragma unroll
        for (int q = 0; q < 4; q++) {
            const float* e = sgh + q * 776 + warp * 97;
            ghr += e[il];
            ghz += e[32 + il];
            ghn += e[64 + il];
        }

        const float rg = 1.f / (1.f + __expf(-(gir + ghr)));
        const float zg = 1.f / (1.f + __expf(-(giz + ghz)));
        const float ng = tanhf(gin + rg * ghn);
        const float hn = (1.f - zg) * ng + zg * hold;
        hold = hn;

        sst[il * 8 + warp] = hn;        // chunk-local layout
        __syncthreads();

        if (s < T_ - 1) {
            // All readers of h(s) everywhere must be done before overwrite.
            mbar_wait_parity(empty_addr, (unsigned)s & 1u);
            // Scatter h(s+1) chunk; per-store release-arrive on target's full.
#pragma unroll
            for (int i = 0; i < 4; i++) {
                float4 v = *(const float4*)&sst[soff[i]];
                st_dsmem_v4(raddr[i], v);
                mbar_arrive_remote(rfull[i]);
            }
        }

        // Off critical path: output stores.
        out[((size_t)s * B_ + bglob) * (2 * H_) + dir * H_ + iglob] = hn;
        if (write_states && s == T_ - 1)
            out[(size_t)T_ * B_ * 2 * H_ + (size_t)(dir * B_ + bglob) * H_ + iglob] = hn;
    }

    CLUSTER_SYNC();                     // no CTA exits with peer DSMEM traffic in flight
}

// ---------------------------------------------------------------------------
extern "C" void kernel_launch(void* const* d_in, const int* in_sizes, int n_in,
                              void* d_out, int out_size)
{
    const float* x    = (const float*)d_in[0];
    const float* h0   = (const float*)d_in[1];
    const float* wihf = (const float*)d_in[2];
    const float* bihf = (const float*)d_in[3];
    const float* whhf = (const float*)d_in[4];
    const float* bhhf = (const float*)d_in[5];
    const float* wihr = (const float*)d_in[6];
    const float* bihr = (const float*)d_in[7];
    const float* whhr = (const float*)d_in[8];
    const float* bhhr = (const float*)d_in[9];
    float* out = (float*)d_out;

    cudaFuncSetAttribute(gru_rec, cudaFuncAttributeMaxDynamicSharedMemorySize, SMEM_REC);
    cudaFuncSetAttribute(gru_rec, cudaFuncAttributeNonPortableClusterSizeAllowed, 1);

    dim3 g1(G_ / 128, (T_ * B_) / 128, 2);
    gi_gemm<<<g1, 256>>>(x, wihf, bihf, wihr, bihr);

    cudaLaunchConfig_t cfg = {};
    cfg.gridDim  = dim3(128, 1, 1);
    cfg.blockDim = dim3(256, 1, 1);
    cfg.dynamicSmemBytes = SMEM_REC;
    cudaLaunchAttribute attrs[1];
    attrs[0].id = cudaLaunchAttributeClusterDimension;
    attrs[0].val.clusterDim = {16, 1, 1};
    cfg.attrs = attrs;
    cfg.numAttrs = 1;
    cudaLaunchKernelEx(&cfg, gru_rec, h0, whhf, bhhf, whhr, bhhr, out, out_size);
}

// round 7
// speedup vs baseline: 2.0785x; 2.0785x over previous
#include <cuda_runtime.h>
#include <cstdint>

// ---------------------------------------------------------------------------
// GRU_2602750181500: bidirectional GRU, T=2048, B=32, F=H=512, fp32.
// Kernel 1: gi = x @ w_ih^T + b_ih (both dirs), fp32 FFMA2 GEMM (~roofline).
// Kernel 2: persistent recurrence, 128 blocks = 2 dirs x 4 bgroups x 16 slices.
//   R7 (on R5's L2-flag scheme): per-warp fine-grained acquire (each GEMV warp
//   polls only its 2 source-slice flags and loads only its 2KB of h), warp-
//   exclusive h regions (no block sync around h), publish via tid0
//   st.release.gpu (no MEMBAR.GPU drains on either side).
// ---------------------------------------------------------------------------

#define T_ 2048
#define B_ 32
#define H_ 512
#define G_ 1536

typedef unsigned long long ull;

__device__ __forceinline__ ull pkf(float lo, float hi) {
    ull r; asm("mov.b64 %0, {%1, %2};" : "=l"(r) : "f"(lo), "f"(hi)); return r;
}
__device__ __forceinline__ void fma2(ull& d, ull a, ull b) {
    asm("fma.rn.f32x2 %0, %1, %2, %0;" : "+l"(d) : "l"(a), "l"(b));
}
__device__ __forceinline__ float2 upk(ull v) {
    float2 f; asm("mov.b64 {%0, %1}, %2;" : "=f"(f.x), "=f"(f.y) : "l"(v)); return f;
}
__device__ __forceinline__ void st_release(unsigned* p, unsigned v) {
    asm volatile("st.release.gpu.global.u32 [%0], %1;" :: "l"(p), "r"(v) : "memory");
}
__device__ __forceinline__ unsigned ld_acquire(const unsigned* p) {
    unsigned v;
    asm volatile("ld.acquire.gpu.global.u32 %0, [%1];" : "=r"(v) : "l"(p) : "memory");
    return v;
}

// Scratch (device globals: allocation-free rule).
__device__ float    g_gi[2][(size_t)T_ * B_ * G_];   // [dir][t*B+b][3H]
__device__ float    g_h[2][4][2][H_ * 8];            // [dir][bgroup][pingpong][k*8+b]
__device__ unsigned g_flags[2][4][16 * 8];           // [dir][bgroup][slice*8]

// ---------------------------------------------------------------------------
// Kernel 1: gi GEMM (FFMA2, unchanged).
// ---------------------------------------------------------------------------
__global__ void __launch_bounds__(256, 2) gi_gemm(
    const float* __restrict__ x,
    const float* __restrict__ wf, const float* __restrict__ bf,
    const float* __restrict__ wr, const float* __restrict__ br)
{
    __shared__ float Xs[8][132];
    __shared__ float Ws[8][132];

    const int tid = threadIdx.x;
    const int dir = blockIdx.z;
    const float* __restrict__ w    = dir ? wr : wf;
    const float* __restrict__ bias = dir ? br : bf;
    float* __restrict__ gi = g_gi[dir];

    const int m0 = blockIdx.y * 128;
    const int n0 = blockIdx.x * 128;

    const int lr = tid >> 1;
    const int lc = (tid & 1) * 4;

    const float* xg = x + (size_t)(m0 + lr) * 512 + lc;
    const float* wg = w + (size_t)(n0 + lr) * 512 + lc;

    const int tx = tid & 15, ty = tid >> 4;

    ull acc[8][4];
#pragma unroll
    for (int i = 0; i < 8; i++)
#pragma unroll
        for (int j = 0; j < 4; j++) acc[i][j] = 0ULL;

    float4 xa = *(const float4*)xg;
    float4 wa = *(const float4*)wg;

    for (int kt = 0; kt < 512; kt += 8) {
        Xs[lc + 0][lr] = xa.x; Xs[lc + 1][lr] = xa.y;
        Xs[lc + 2][lr] = xa.z; Xs[lc + 3][lr] = xa.w;
        Ws[lc + 0][lr] = wa.x; Ws[lc + 1][lr] = wa.y;
        Ws[lc + 2][lr] = wa.z; Ws[lc + 3][lr] = wa.w;
        __syncthreads();
        if (kt + 8 < 512) {
            xa = *(const float4*)(xg + kt + 8);
            wa = *(const float4*)(wg + kt + 8);
        }
#pragma unroll
        for (int kk = 0; kk < 8; kk++) {
            float4 a0 = *(const float4*)&Xs[kk][ty * 8];
            float4 a1 = *(const float4*)&Xs[kk][ty * 8 + 4];
            float4 b0 = *(const float4*)&Ws[kk][tx * 8];
            float4 b1 = *(const float4*)&Ws[kk][tx * 8 + 4];
            ull bq[4] = { pkf(b0.x, b0.y), pkf(b0.z, b0.w),
                          pkf(b1.x, b1.y), pkf(b1.z, b1.w) };
            float av[8] = { a0.x, a0.y, a0.z, a0.w, a1.x, a1.y, a1.z, a1.w };
#pragma unroll
            for (int i = 0; i < 8; i++) {
                ull aq = pkf(av[i], av[i]);
#pragma unroll
                for (int j = 0; j < 4; j++) fma2(acc[i][j], aq, bq[j]);
            }
        }
        __syncthreads();
    }

    float bb2[8];
#pragma unroll
    for (int j = 0; j < 8; j++) bb2[j] = bias[n0 + tx * 8 + j];
#pragma unroll
    for (int i = 0; i < 8; i++) {
        float* cp = gi + (size_t)(m0 + ty * 8 + i) * G_ + n0 + tx * 8;
#pragma unroll
        for (int j = 0; j < 4; j++) {
            float2 v = upk(acc[i][j]);
            v.x += bb2[2 * j]; v.y += bb2[2 * j + 1];
            *(float2*)(cp + 2 * j) = v;
        }
    }
}

// ---------------------------------------------------------------------------
// Kernel 2: persistent recurrence.
// SMEM: sw [96][513] | sh [512][8] (warp-exclusive 512-float regions) |
//       sgh [4][8][97]
// ---------------------------------------------------------------------------
#define SW2      513
#define OFF_H    (96 * SW2)              // 49248
#define OFF_GH   (OFF_H + 512 * 8)       // 53344
#define SMEM_TOT (OFF_GH + 4 * 776)      // 56448 floats = 225792 B
#define SMEM_REC (SMEM_TOT * 4)

__global__ void __launch_bounds__(256, 1) gru_rec(
    const float* __restrict__ h0,
    const float* __restrict__ whh_f, const float* __restrict__ bhh_f,
    const float* __restrict__ whh_r, const float* __restrict__ bhh_r,
    float* __restrict__ out, int out_size)
{
    extern __shared__ float smem[];
    float* sw  = smem;              // [96 r][513]
    float* sh  = smem + OFF_H;      // [512 k][8 b]; warp w owns k in [64w,64w+64)
    float* sgh = smem + OFF_GH;     // [4 khp][8 b][97]

    const int tid  = threadIdx.x;
    const int warp = tid >> 5;
    const int lane = tid & 31;
    const int bid = blockIdx.x;
    const int dir = bid >> 6;
    const int bg  = (bid >> 4) & 3;
    const int sl  = bid & 15;

    const float* __restrict__ whh = dir ? whh_r : whh_f;
    const float* __restrict__ bhh = dir ? bhh_r : bhh_f;
    const float* __restrict__ gi  = g_gi[dir];
    unsigned* flags = &g_flags[dir][bg][0];
    const unsigned base = ld_acquire(flags + sl * 8);

    // Load 96 w_hh rows into SMEM (stride 513: conflict-free LDS.32).
    for (int idx = tid; idx < 96 * 128; idx += 256) {
        int r = idx >> 7, c4 = (idx & 127) << 2;
        int gate = r >> 5, il2 = r & 31;
        float4 v = *(const float4*)&whh[(size_t)((gate << 9) + sl * 32 + il2) * 512 + c4];
        float* d = &sw[r * SW2 + c4];
        d[0] = v.x; d[1] = v.y; d[2] = v.z; d[3] = v.w;
    }

    // Epilogue mapping: b == warp, il == lane.
    const int il = lane;
    const int iglob = sl * 32 + il;
    const int bglob = bg * 8 + warp;

    float* hbuf0 = g_h[dir][bg][0];
    float* hbuf1 = g_h[dir][bg][1];

    float hold = h0[(size_t)(dir * B_ + bglob) * H_ + iglob];
    hbuf0[iglob * 8 + warp] = hold;    // publish own chunk of h(0)

    const float bh_r = bhh[iglob];
    const float bh_z = bhh[512 + iglob];
    const float bh_n = bhh[1024 + iglob];

    __syncthreads();
    if (tid == 0) st_release(flags + sl * 8, base + 1);

    const bool write_states = (out_size > T_ * B_ * 2 * H_);

    // GEMV pointers: warp = k-chunk (64 k), lane = base row (3 rows/thread).
    const float* wp0 = sw + lane * SW2 + warp * 64;
    const float* wp1 = wp0 + 32 * SW2;
    const float* wp2 = wp0 + 64 * SW2;

    // This warp consumes h chunks produced by slices 2*warp and 2*warp+1.
    const int src_flag = (2 * warp + (lane & 1)) * 8;

    for (int s = 0; s < T_; s++) {
        const int xrow = dir ? (T_ - 1 - s) : s;

        // gi loads issued before the poll (latency hidden under poll+GEMV).
        const float* gp = gi + ((size_t)xrow * B_ + bglob) * G_ + iglob;
        const float gir = __ldcs(gp);
        const float giz = __ldcs(gp + 512);
        const float gin = __ldcs(gp + 1024);

        // Per-warp acquire: only this warp's two source slices must be ready.
        {
            const unsigned target = base + 1 + (unsigned)s;
            while (ld_acquire(flags + src_flag) < target) __nanosleep(40);
            __syncwarp();
        }

        const float* hsrc = (s & 1) ? hbuf1 : hbuf0;
        float*       hdst = (s & 1) ? hbuf0 : hbuf1;

        // Per-warp load of own 2KB h range (k in [64*warp, 64*warp+64)).
        {
            const float4* src = (const float4*)hsrc + warp * 128 + lane;
            float4* dst = (float4*)sh + warp * 128 + lane;
#pragma unroll
            for (int i = 0; i < 4; i++)
                dst[i * 32] = __ldcg(src + i * 32);
        }
        // No sync needed: sh region is warp-exclusive (written+read by this warp).

        // GEMV: 3 rows x 8 batches x 64 k per thread.
        ull a0[4], a1[4], a2[4];
#pragma unroll
        for (int j = 0; j < 4; j++) { a0[j] = 0; a1[j] = 0; a2[j] = 0; }

        const ull* hp = (const ull*)sh + (size_t)warp * 64 * 4;
#pragma unroll 4
        for (int kk = 0; kk < 64; kk++) {
            const float w0 = wp0[kk];
            const float w1 = wp1[kk];
            const float w2 = wp2[kk];
            ulonglong2 hA = *(const ulonglong2*)(hp + (size_t)kk * 4);
            ulonglong2 hB = *(const ulonglong2*)(hp + (size_t)kk * 4 + 2);
            const ull q0 = pkf(w0, w0);
            fma2(a0[0], q0, hA.x); fma2(a0[1], q0, hA.y);
            fma2(a0[2], q0, hB.x); fma2(a0[3], q0, hB.y);
            const ull q1 = pkf(w1, w1);
            fma2(a1[0], q1, hA.x); fma2(a1[1], q1, hA.y);
            fma2(a1[2], q1, hB.x); fma2(a1[3], q1, hB.y);
            const ull q2 = pkf(w2, w2);
            fma2(a2[0], q2, hA.x); fma2(a2[1], q2, hA.y);
            fma2(a2[2], q2, hB.x); fma2(a2[3], q2, hB.y);
        }

        // Reduction stage 1: warps 0-3 store partials ([khp][b][97]).
        float* sb = sgh + (warp & 3) * 776;
        if (warp < 4) {
#pragma unroll
            for (int j = 0; j < 4; j++) {
                float2 p;
                p = upk(a0[j]);
                sb[(2 * j) * 97 + lane]          = p.x;
                sb[(2 * j + 1) * 97 + lane]      = p.y;
                p = upk(a1[j]);
                sb[(2 * j) * 97 + 32 + lane]     = p.x;
                sb[(2 * j + 1) * 97 + 32 + lane] = p.y;
                p = upk(a2[j]);
                sb[(2 * j) * 97 + 64 + lane]     = p.x;
                sb[(2 * j + 1) * 97 + 64 + lane] = p.y;
            }
        }
        __syncthreads();
        // Stage 2: warps 4-7 add their partials.
        if (warp >= 4) {
#pragma unroll
            for (int j = 0; j < 4; j++) {
                float2 p;
                p = upk(a0[j]);
                sb[(2 * j) * 97 + lane]          += p.x;
                sb[(2 * j + 1) * 97 + lane]      += p.y;
                p = upk(a1[j]);
                sb[(2 * j) * 97 + 32 + lane]     += p.x;
                sb[(2 * j + 1) * 97 + 32 + lane] += p.y;
                p = upk(a2[j]);
                sb[(2 * j) * 97 + 64 + lane]     += p.x;
                sb[(2 * j + 1) * 97 + 64 + lane] += p.y;
            }
        }
        __syncthreads();

        // Epilogue: b = warp, il = lane.
        float ghr = bh_r, ghz = bh_z, ghn = bh_n;
#pragma unroll
        for (int q = 0; q < 4; q++) {
            const float* e = sgh + q * 776 + warp * 97;
            ghr += e[il];
            ghz += e[32 + il];
            ghn += e[64 + il];
        }

        const float rg = 1.f / (1.f + __expf(-(gir + ghr)));
        const float zg = 1.f / (1.f + __expf(-(giz + ghz)));
        const float ng = tanhf(gin + rg * ghn);
        const float hn = (1.f - zg) * ng + zg * hold;
        hold = hn;

        __stcg(&hdst[iglob * 8 + warp], hn);
        __syncthreads();                 // all hn stores issued before release
        if (tid == 0) st_release(flags + sl * 8, base + 2 + (unsigned)s);

        // Off critical path: output stores.
        out[((size_t)s * B_ + bglob) * (2 * H_) + dir * H_ + iglob] = hn;
        if (write_states && s == T_ - 1)
            out[(size_t)T_ * B_ * 2 * H_ + (size_t)(dir * B_ + bglob) * H_ + iglob] = hn;
    }
}

// ---------------------------------------------------------------------------
extern "C" void kernel_launch(void* const* d_in, const int* in_sizes, int n_in,
                              void* d_out, int out_size)
{
    const float* x    = (const float*)d_in[0];
    const float* h0   = (const float*)d_in[1];
    const float* wihf = (const float*)d_in[2];
    const float* bihf = (const float*)d_in[3];
    const float* whhf = (const float*)d_in[4];
    const float* bhhf = (const float*)d_in[5];
    const float* wihr = (const float*)d_in[6];
    const float* bihr = (const float*)d_in[7];
    const float* whhr = (const float*)d_in[8];
    const float* bhhr = (const float*)d_in[9];
    float* out = (float*)d_out;

    cudaFuncSetAttribute(gru_rec, cudaFuncAttributeMaxDynamicSharedMemorySize, SMEM_REC);

    dim3 g1(G_ / 128, (T_ * B_) / 128, 2);
    gi_gemm<<<g1, 256>>>(x, wihf, bihf, wihr, bihr);

    gru_rec<<<128, 256, SMEM_REC>>>(h0, whhf, bhhf, whhr, bhhr, out, out_size);
}

// round 8
// speedup vs baseline: 2.6250x; 1.2629x over previous
#include <cuda_runtime.h>
#include <cuda_bf16.h>
#include <cstdint>

// ---------------------------------------------------------------------------
// GRU_2602750181500: bidirectional GRU, T=2048, B=32, F=H=512, fp32.
// R8: gi GEMM moved to bf16 tensor cores (mma.sync m16n8k16) with 2-term
//     bf16 split (xh*wh + xh*wl + xl*wh; xl*wl negligible ~2e-6).
//     Recurrence kernel identical to R7 (13.33ms run, 4.6us/step).
// ---------------------------------------------------------------------------

#define T_ 2048
#define B_ 32
#define H_ 512
#define G_ 1536

typedef unsigned long long ull;

__device__ __forceinline__ ull pkf(float lo, float hi) {
    ull r; asm("mov.b64 %0, {%1, %2};" : "=l"(r) : "f"(lo), "f"(hi)); return r;
}
__device__ __forceinline__ void fma2(ull& d, ull a, ull b) {
    asm("fma.rn.f32x2 %0, %1, %2, %0;" : "+l"(d) : "l"(a), "l"(b));
}
__device__ __forceinline__ float2 upk(ull v) {
    float2 f; asm("mov.b64 {%0, %1}, %2;" : "=f"(f.x), "=f"(f.y) : "l"(v)); return f;
}
__device__ __forceinline__ void st_release(unsigned* p, unsigned v) {
    asm volatile("st.release.gpu.global.u32 [%0], %1;" :: "l"(p), "r"(v) : "memory");
}
__device__ __forceinline__ unsigned ld_acquire(const unsigned* p) {
    unsigned v;
    asm volatile("ld.acquire.gpu.global.u32 %0, [%1];" : "=r"(v) : "l"(p) : "memory");
    return v;
}
__device__ __forceinline__ uint32_t smem_u32(const void* p) {
    uint32_t a;
    asm("{ .reg .u64 t; cvta.to.shared.u64 t, %1; cvt.u32.u64 %0, t; }"
        : "=r"(a) : "l"(p));
    return a;
}

#define LDSM4(r, addr) \
    asm volatile("ldmatrix.sync.aligned.m8n8.x4.shared.b16 {%0,%1,%2,%3}, [%4];" \
        : "=r"((r)[0]), "=r"((r)[1]), "=r"((r)[2]), "=r"((r)[3]) : "r"(addr))

#define MMA_BF16(d, a, b0, b1) \
    asm volatile("mma.sync.aligned.m16n8k16.row.col.f32.bf16.bf16.f32 " \
        "{%0,%1,%2,%3}, {%4,%5,%6,%7}, {%8,%9}, {%0,%1,%2,%3};" \
        : "+f"((d)[0]), "+f"((d)[1]), "+f"((d)[2]), "+f"((d)[3]) \
        : "r"((a)[0]), "r"((a)[1]), "r"((a)[2]), "r"((a)[3]), "r"(b0), "r"(b1))

// Scratch (device globals: allocation-free rule).
__device__ float          g_gi[2][(size_t)T_ * B_ * G_];   // [dir][t*B+b][3H]
__device__ float          g_h[2][4][2][H_ * 8];
__device__ unsigned       g_flags[2][4][16 * 8];
__device__ __nv_bfloat16  g_xh[(size_t)T_ * B_ * 512];
__device__ __nv_bfloat16  g_xl[(size_t)T_ * B_ * 512];
__device__ __nv_bfloat16  g_wh[2][(size_t)G_ * 512];
__device__ __nv_bfloat16  g_wl[2][(size_t)G_ * 512];

// ---------------------------------------------------------------------------
// Split-conversion: v -> hi = bf16(v), lo = bf16(v - hi).
// ---------------------------------------------------------------------------
__global__ void conv_split(const float4* __restrict__ src,
                           __nv_bfloat162* __restrict__ hi,
                           __nv_bfloat162* __restrict__ lo, int n4)
{
    int i = blockIdx.x * blockDim.x + threadIdx.x;
    if (i >= n4) return;
    float4 v = src[i];
    __nv_bfloat16 h0 = __float2bfloat16(v.x), h1 = __float2bfloat16(v.y);
    __nv_bfloat16 h2 = __float2bfloat16(v.z), h3 = __float2bfloat16(v.w);
    hi[2 * i]     = __nv_bfloat162(h0, h1);
    hi[2 * i + 1] = __nv_bfloat162(h2, h3);
    lo[2 * i]     = __nv_bfloat162(__float2bfloat16(v.x - __bfloat162float(h0)),
                                   __float2bfloat16(v.y - __bfloat162float(h1)));
    lo[2 * i + 1] = __nv_bfloat162(__float2bfloat16(v.z - __bfloat162float(h2)),
                                   __float2bfloat16(v.w - __bfloat162float(h3)));
}

// ---------------------------------------------------------------------------
// Kernel 1: gi GEMM via HMMA. C[m][n] = sum_k x[m][k]*w[n][k] + bias[n].
// 128x128 tile per block, 256 thr (8 warps: 2 m x 4 n), K chunks of 32,
// double-buffered SMEM. 3 mma combos (hh, hl, lh) share fp32 accumulators.
//
// Fragment mapping (verified against PTX spec):
//  A (row-major, [m][k] SMEM): ldmatrix.x4, addr lane L:
//    row = m0+(L&15), k8 = L>>4  -> tiles (m0-7,k0-7),(m8-15,k0-7),(m0-7,k8-15),
//    (m8-15,k8-15) = a0..a3. Spec a0:(m=t/4,k=2(t%4)) matches non-trans tile.
//  B ([n][k] row-major == col-major (k,n)): ldmatrix.x4, addr lane L:
//    row = n0+(L&7)+((L>>4)<<3), k8 = (L>>3)&1 -> regs {n0-7@k0, n0-7@k8,
//    n8-15@k0, n8-15@k8}: frag nt even = {r0,r1}, nt odd = {r2,r3}.
//    Spec b0:(k=2(t%4), n=t/4) = non-trans tile with rows=n, cols=k. OK.
// ---------------------------------------------------------------------------
#define PADB 40                           // bf16 per SMEM row (80B: ldmatrix conflict-free)
#define ARRE (128 * PADB)                 // bf16 per array (5120)
#define ARRB (ARRE * 2)                   // bytes per array (10240)
#define STGB (4 * ARRB)                   // bytes per stage (40960)
#define GEMM_SMEM (2 * STGB)              // 81920 B

__global__ void __launch_bounds__(256, 1) gi_gemm_tc(
    const float* __restrict__ bf, const float* __restrict__ br)
{
    extern __shared__ __nv_bfloat16 sm[];

    const int tid  = threadIdx.x;
    const int lane = tid & 31;
    const int warp = tid >> 5;
    const int dir  = blockIdx.z;
    const int n0   = blockIdx.x * 128;
    const int m0   = blockIdx.y * 128;

    const __nv_bfloat16* __restrict__ xh = g_xh;
    const __nv_bfloat16* __restrict__ xl = g_xl;
    const __nv_bfloat16* __restrict__ wh = g_wh[dir];
    const __nv_bfloat16* __restrict__ wl = g_wl[dir];
    const float* __restrict__ bias = dir ? br : bf;
    float* __restrict__ gi = g_gi[dir];

    // Global load mapping: 512 float4 per array; thread covers rows r0, r0+64.
    const int r0 = tid >> 2;
    const int c8 = (tid & 3) * 8;
    const __nv_bfloat16* pxh = xh + (size_t)(m0 + r0) * 512 + c8;
    const __nv_bfloat16* pxl = xl + (size_t)(m0 + r0) * 512 + c8;
    const __nv_bfloat16* pwh = wh + (size_t)(n0 + r0) * 512 + c8;
    const __nv_bfloat16* pwl = wl + (size_t)(n0 + r0) * 512 + c8;
    const size_t rstep = (size_t)64 * 512;

    const int so0 = r0 * PADB + c8;          // bf16 units
    const int so1 = (r0 + 64) * PADB + c8;

    // ldmatrix per-lane byte offsets (within array, before stage/arr/mt/kk).
    const int wm = warp >> 2, wn = warp & 3;
    const int a_row = wm * 64 + (lane & 15);
    const int a_off = (a_row * PADB + (lane >> 4) * 8) * 2;
    const int b_row = wn * 32 + (lane & 7) + ((lane >> 4) << 3);
    const int b_off = (b_row * PADB + ((lane >> 3) & 1) * 8) * 2;

    const uint32_t smb = smem_u32(sm);

    float acc[4][4][4];
#pragma unroll
    for (int i = 0; i < 4; i++)
#pragma unroll
        for (int j = 0; j < 4; j++)
#pragma unroll
            for (int q = 0; q < 4; q++) acc[i][j][q] = 0.f;

    float4 vh0, vh1, vl0, vl1, uh0, uh1, ul0, ul1;
    // chunk 0 loads
    vh0 = *(const float4*)(pxh); vh1 = *(const float4*)(pxh + rstep);
    vl0 = *(const float4*)(pxl); vl1 = *(const float4*)(pxl + rstep);
    uh0 = *(const float4*)(pwh); uh1 = *(const float4*)(pwh + rstep);
    ul0 = *(const float4*)(pwl); ul1 = *(const float4*)(pwl + rstep);
    {
        float4* s = (float4*)sm;
        *(float4*)&sm[0 * ARRE + so0] = vh0; *(float4*)&sm[0 * ARRE + so1] = vh1;
        *(float4*)&sm[1 * ARRE + so0] = vl0; *(float4*)&sm[1 * ARRE + so1] = vl1;
        *(float4*)&sm[2 * ARRE + so0] = uh0; *(float4*)&sm[2 * ARRE + so1] = uh1;
        *(float4*)&sm[3 * ARRE + so0] = ul0; *(float4*)&sm[3 * ARRE + so1] = ul1;
        (void)s;
    }
    __syncthreads();

    for (int c = 0; c < 16; c++) {
        const int st = c & 1;
        if (c < 15) {
            const int k0 = (c + 1) * 32;
            vh0 = *(const float4*)(pxh + k0); vh1 = *(const float4*)(pxh + k0 + rstep);
            vl0 = *(const float4*)(pxl + k0); vl1 = *(const float4*)(pxl + k0 + rstep);
            uh0 = *(const float4*)(pwh + k0); uh1 = *(const float4*)(pwh + k0 + rstep);
            ul0 = *(const float4*)(pwl + k0); ul1 = *(const float4*)(pwl + k0 + rstep);
        }

        const uint32_t sb = smb + st * STGB;
#pragma unroll
        for (int kk = 0; kk < 2; kk++) {
            const uint32_t kby = kk * 32;          // 16 bf16 = 32 bytes
            uint32_t ah[4][4], al[4][4], bh[2][4], bl[2][4];
#pragma unroll
            for (int mt = 0; mt < 4; mt++) {
                LDSM4(ah[mt], sb + 0 * ARRB + a_off + mt * (16 * PADB * 2) + kby);
                LDSM4(al[mt], sb + 1 * ARRB + a_off + mt * (16 * PADB * 2) + kby);
            }
#pragma unroll
            for (int np = 0; np < 2; np++) {
                LDSM4(bh[np], sb + 2 * ARRB + b_off + np * (16 * PADB * 2) + kby);
                LDSM4(bl[np], sb + 3 * ARRB + b_off + np * (16 * PADB * 2) + kby);
            }
#pragma unroll
            for (int mt = 0; mt < 4; mt++) {
#pragma unroll
                for (int nt = 0; nt < 4; nt++) {
                    const int np = nt >> 1, hf = (nt & 1) * 2;
                    MMA_BF16(acc[mt][nt], ah[mt], bh[np][hf], bh[np][hf + 1]);
                    MMA_BF16(acc[mt][nt], ah[mt], bl[np][hf], bl[np][hf + 1]);
                    MMA_BF16(acc[mt][nt], al[mt], bh[np][hf], bh[np][hf + 1]);
                }
            }
        }
        __syncthreads();
        if (c < 15) {
            const int os = (st ^ 1) * (STGB / 2);  // bf16 units per stage = STGB/2
            *(float4*)&sm[os + 0 * ARRE + so0] = vh0; *(float4*)&sm[os + 0 * ARRE + so1] = vh1;
            *(float4*)&sm[os + 1 * ARRE + so0] = vl0; *(float4*)&sm[os + 1 * ARRE + so1] = vl1;
            *(float4*)&sm[os + 2 * ARRE + so0] = uh0; *(float4*)&sm[os + 2 * ARRE + so1] = uh1;
            *(float4*)&sm[os + 3 * ARRE + so0] = ul0; *(float4*)&sm[os + 3 * ARRE + so1] = ul1;
            __syncthreads();
        }
    }

    // Epilogue: c0,c1 -> (m, n..n+1); c2,c3 -> (m+8, n..n+1).
#pragma unroll
    for (int mt = 0; mt < 4; mt++) {
        const int m = m0 + wm * 64 + mt * 16 + (lane >> 2);
#pragma unroll
        for (int nt = 0; nt < 4; nt++) {
            const int n = n0 + wn * 32 + nt * 8 + (lane & 3) * 2;
            const float b0 = bias[n], b1 = bias[n + 1];
            *(float2*)&gi[(size_t)m * G_ + n] =
                make_float2(acc[mt][nt][0] + b0, acc[mt][nt][1] + b1);
            *(float2*)&gi[(size_t)(m + 8) * G_ + n] =
                make_float2(acc[mt][nt][2] + b0, acc[mt][nt][3] + b1);
        }
    }
}

// ---------------------------------------------------------------------------
// Kernel 2: persistent recurrence — IDENTICAL to R7 (13.33ms run).
// ---------------------------------------------------------------------------
#define SW2      513
#define OFF_H    (96 * SW2)
#define OFF_GH   (OFF_H + 512 * 8)
#define SMEM_TOT (OFF_GH + 4 * 776)
#define SMEM_REC (SMEM_TOT * 4)

__global__ void __launch_bounds__(256, 1) gru_rec(
    const float* __restrict__ h0,
    const float* __restrict__ whh_f, const float* __restrict__ bhh_f,
    const float* __restrict__ whh_r, const float* __restrict__ bhh_r,
    float* __restrict__ out, int out_size)
{
    extern __shared__ float smem[];
    float* sw  = smem;
    float* sh  = smem + OFF_H;
    float* sgh = smem + OFF_GH;

    const int tid  = threadIdx.x;
    const int warp = tid >> 5;
    const int lane = tid & 31;
    const int bid = blockIdx.x;
    const int dir = bid >> 6;
    const int bg  = (bid >> 4) & 3;
    const int sl  = bid & 15;

    const float* __restrict__ whh = dir ? whh_r : whh_f;
    const float* __restrict__ bhh = dir ? bhh_r : bhh_f;
    const float* __restrict__ gi  = g_gi[dir];
    unsigned* flags = &g_flags[dir][bg][0];
    const unsigned base = ld_acquire(flags + sl * 8);

    for (int idx = tid; idx < 96 * 128; idx += 256) {
        int r = idx >> 7, c4 = (idx & 127) << 2;
        int gate = r >> 5, il2 = r & 31;
        float4 v = *(const float4*)&whh[(size_t)((gate << 9) + sl * 32 + il2) * 512 + c4];
        float* d = &sw[r * SW2 + c4];
        d[0] = v.x; d[1] = v.y; d[2] = v.z; d[3] = v.w;
    }

    const int il = lane;
    const int iglob = sl * 32 + il;
    const int bglob = bg * 8 + warp;

    float* hbuf0 = g_h[dir][bg][0];
    float* hbuf1 = g_h[dir][bg][1];

    float hold = h0[(size_t)(dir * B_ + bglob) * H_ + iglob];
    hbuf0[iglob * 8 + warp] = hold;

    const float bh_r = bhh[iglob];
    const float bh_z = bhh[512 + iglob];
    const float bh_n = bhh[1024 + iglob];

    __syncthreads();
    if (tid == 0) st_release(flags + sl * 8, base + 1);

    const bool write_states = (out_size > T_ * B_ * 2 * H_);

    const float* wp0 = sw + lane * SW2 + warp * 64;
    const float* wp1 = wp0 + 32 * SW2;
    const float* wp2 = wp0 + 64 * SW2;

    const int src_flag = (2 * warp + (lane & 1)) * 8;

    for (int s = 0; s < T_; s++) {
        const int xrow = dir ? (T_ - 1 - s) : s;

        const float* gp = gi + ((size_t)xrow * B_ + bglob) * G_ + iglob;
        const float gir = __ldcs(gp);
        const float giz = __ldcs(gp + 512);
        const float gin = __ldcs(gp + 1024);

        {
            const unsigned target = base + 1 + (unsigned)s;
            while (ld_acquire(flags + src_flag) < target) __nanosleep(40);
            __syncwarp();
        }

        const float* hsrc = (s & 1) ? hbuf1 : hbuf0;
        float*       hdst = (s & 1) ? hbuf0 : hbuf1;

        {
            const float4* src = (const float4*)hsrc + warp * 128 + lane;
            float4* dst = (float4*)sh + warp * 128 + lane;
#pragma unroll
            for (int i = 0; i < 4; i++)
                dst[i * 32] = __ldcg(src + i * 32);
        }

        ull a0[4], a1[4], a2[4];
#pragma unroll
        for (int j = 0; j < 4; j++) { a0[j] = 0; a1[j] = 0; a2[j] = 0; }

        const ull* hp = (const ull*)sh + (size_t)warp * 64 * 4;
#pragma unroll 4
        for (int kk = 0; kk < 64; kk++) {
            const float w0 = wp0[kk];
            const float w1 = wp1[kk];
            const float w2 = wp2[kk];
            ulonglong2 hA = *(const ulonglong2*)(hp + (size_t)kk * 4);
            ulonglong2 hB = *(const ulonglong2*)(hp + (size_t)kk * 4 + 2);
            const ull q0 = pkf(w0, w0);
            fma2(a0[0], q0, hA.x); fma2(a0[1], q0, hA.y);
            fma2(a0[2], q0, hB.x); fma2(a0[3], q0, hB.y);
            const ull q1 = pkf(w1, w1);
            fma2(a1[0], q1, hA.x); fma2(a1[1], q1, hA.y);
            fma2(a1[2], q1, hB.x); fma2(a1[3], q1, hB.y);
            const ull q2 = pkf(w2, w2);
            fma2(a2[0], q2, hA.x); fma2(a2[1], q2, hA.y);
            fma2(a2[2], q2, hB.x); fma2(a2[3], q2, hB.y);
        }

        float* sb = sgh + (warp & 3) * 776;
        if (warp < 4) {
#pragma unroll
            for (int j = 0; j < 4; j++) {
                float2 p;
                p = upk(a0[j]);
                sb[(2 * j) * 97 + lane]          = p.x;
                sb[(2 * j + 1) * 97 + lane]      = p.y;
                p = upk(a1[j]);
                sb[(2 * j) * 97 + 32 + lane]     = p.x;
                sb[(2 * j + 1) * 97 + 32 + lane] = p.y;
                p = upk(a2[j]);
                sb[(2 * j) * 97 + 64 + lane]     = p.x;
                sb[(2 * j + 1) * 97 + 64 + lane] = p.y;
            }
        }
        __syncthreads();
        if (warp >= 4) {
#pragma unroll
            for (int j = 0; j < 4; j++) {
                float2 p;
                p = upk(a0[j]);
                sb[(2 * j) * 97 + lane]          += p.x;
                sb[(2 * j + 1) * 97 + lane]      += p.y;
                p = upk(a1[j]);
                sb[(2 * j) * 97 + 32 + lane]     += p.x;
                sb[(2 * j + 1) * 97 + 32 + lane] += p.y;
                p = upk(a2[j]);
                sb[(2 * j) * 97 + 64 + lane]     += p.x;
                sb[(2 * j + 1) * 97 + 64 + lane] += p.y;
            }
        }
        __syncthreads();

        float ghr = bh_r, ghz = bh_z, ghn = bh_n;
#pragma unroll
        for (int q = 0; q < 4; q++) {
            const float* e = sgh + q * 776 + warp * 97;
            ghr += e[il];
            ghz += e[32 + il];
            ghn += e[64 + il];
        }

        const float rg = 1.f / (1.f + __expf(-(gir + ghr)));
        const float zg = 1.f / (1.f + __expf(-(giz + ghz)));
        const float ng = tanhf(gin + rg * ghn);
        const float hn = (1.f - zg) * ng + zg * hold;
        hold = hn;

        __stcg(&hdst[iglob * 8 + warp], hn);
        __syncthreads();
        if (tid == 0) st_release(flags + sl * 8, base + 2 + (unsigned)s);

        out[((size_t)s * B_ + bglob) * (2 * H_) + dir * H_ + iglob] = hn;
        if (write_states && s == T_ - 1)
            out[(size_t)T_ * B_ * 2 * H_ + (size_t)(dir * B_ + bglob) * H_ + iglob] = hn;
    }
}

// ---------------------------------------------------------------------------
extern "C" void kernel_launch(void* const* d_in, const int* in_sizes, int n_in,
                              void* d_out, int out_size)
{
    const float* x    = (const float*)d_in[0];
    const float* h0   = (const float*)d_in[1];
    const float* wihf = (const float*)d_in[2];
    const float* bihf = (const float*)d_in[3];
    const float* whhf = (const float*)d_in[4];
    const float* bhhf = (const float*)d_in[5];
    const float* wihr = (const float*)d_in[6];
    const float* bihr = (const float*)d_in[7];
    const float* whhr = (const float*)d_in[8];
    const float* bhhr = (const float*)d_in[9];
    float* out = (float*)d_out;

    __nv_bfloat16 *xh_p, *xl_p, *wh_p, *wl_p;
    cudaGetSymbolAddress((void**)&xh_p, g_xh);
    cudaGetSymbolAddress((void**)&xl_p, g_xl);
    cudaGetSymbolAddress((void**)&wh_p, g_wh);
    cudaGetSymbolAddress((void**)&wl_p, g_wl);

    // Split conversions.
    {
        int n4 = (T_ * B_ * 512) / 4;
        conv_split<<<(n4 + 255) / 256, 256>>>((const float4*)x,
            (__nv_bfloat162*)xh_p, (__nv_bfloat162*)xl_p, n4);
        int w4 = (G_ * 512) / 4;
        conv_split<<<(w4 + 255) / 256, 256>>>((const float4*)wihf,
            (__nv_bfloat162*)wh_p, (__nv_bfloat162*)wl_p, w4);
        conv_split<<<(w4 + 255) / 256, 256>>>((const float4*)wihr,
            (__nv_bfloat162*)(wh_p + (size_t)G_ * 512),
            (__nv_bfloat162*)(wl_p + (size_t)G_ * 512), w4);
    }

    cudaFuncSetAttribute(gi_gemm_tc, cudaFuncAttributeMaxDynamicSharedMemorySize, GEMM_SMEM);
    dim3 g1(G_ / 128, (T_ * B_) / 128, 2);
    gi_gemm_tc<<<g1, 256, GEMM_SMEM>>>(bihf, bihr);

    cudaFuncSetAttribute(gru_rec, cudaFuncAttributeMaxDynamicSharedMemorySize, SMEM_REC);
    gru_rec<<<128, 256, SMEM_REC>>>(h0, whhf, bhhf, whhr, bhhr, out, out_size);
}

// round 9
// speedup vs baseline: 3.0924x; 1.1781x over previous
#include <cuda_runtime.h>
#include <cuda_bf16.h>
#include <cstdint>

// ---------------------------------------------------------------------------
// GRU_2602750181500: bidirectional GRU, T=2048, B=32, F=H=512, fp32.
// R9: recurrence GEMV moved to HMMA (m16n8k16) with 2-term bf16 splits on
//     both w_hh and h (wh*hh + wh*hl + wl*hh). h published as bf16 hi/lo.
//     Per-warp fine acquire + L2 flag sync kept from R7. GEMM from R8.
// ---------------------------------------------------------------------------

#define T_ 2048
#define B_ 32
#define H_ 512
#define G_ 1536

typedef unsigned long long ull;

__device__ __forceinline__ ull pkf(float lo, float hi) {
    ull r; asm("mov.b64 %0, {%1, %2};" : "=l"(r) : "f"(lo), "f"(hi)); return r;
}
__device__ __forceinline__ void fma2(ull& d, ull a, ull b) {
    asm("fma.rn.f32x2 %0, %1, %2, %0;" : "+l"(d) : "l"(a), "l"(b));
}
__device__ __forceinline__ float2 upk(ull v) {
    float2 f; asm("mov.b64 {%0, %1}, %2;" : "=f"(f.x), "=f"(f.y) : "l"(v)); return f;
}
__device__ __forceinline__ void st_release(unsigned* p, unsigned v) {
    asm volatile("st.release.gpu.global.u32 [%0], %1;" :: "l"(p), "r"(v) : "memory");
}
__device__ __forceinline__ unsigned ld_acquire(const unsigned* p) {
    unsigned v;
    asm volatile("ld.acquire.gpu.global.u32 %0, [%1];" : "=r"(v) : "l"(p) : "memory");
    return v;
}
__device__ __forceinline__ uint32_t smem_u32(const void* p) {
    uint32_t a;
    asm("{ .reg .u64 t; cvta.to.shared.u64 t, %1; cvt.u32.u64 %0, t; }"
        : "=r"(a) : "l"(p));
    return a;
}
__device__ __forceinline__ void st_cg_u16(unsigned short* p, unsigned short v) {
    asm volatile("st.global.cg.u16 [%0], %1;" :: "l"(p), "h"(v) : "memory");
}

#define LDSM4(r, addr) \
    asm volatile("ldmatrix.sync.aligned.m8n8.x4.shared.b16 {%0,%1,%2,%3}, [%4];" \
        : "=r"((r)[0]), "=r"((r)[1]), "=r"((r)[2]), "=r"((r)[3]) : "r"(addr))

#define MMA_BF16(d, a, b0, b1) \
    asm volatile("mma.sync.aligned.m16n8k16.row.col.f32.bf16.bf16.f32 " \
        "{%0,%1,%2,%3}, {%4,%5,%6,%7}, {%8,%9}, {%0,%1,%2,%3};" \
        : "+f"((d)[0]), "+f"((d)[1]), "+f"((d)[2]), "+f"((d)[3]) \
        : "r"((a)[0]), "r"((a)[1]), "r"((a)[2]), "r"((a)[3]), "r"(b0), "r"(b1))

// Scratch (device globals: allocation-free rule).
__device__ float          g_gi[2][(size_t)T_ * B_ * G_];
__device__ unsigned short g_hh[2][4][2][8][512];   // h high bf16 [dir][bg][pp][b][k]
__device__ unsigned short g_hl[2][4][2][8][512];   // h low  bf16
__device__ unsigned       g_flags[2][4][16 * 8];
__device__ __nv_bfloat16  g_xh[(size_t)T_ * B_ * 512];
__device__ __nv_bfloat16  g_xl[(size_t)T_ * B_ * 512];
__device__ __nv_bfloat16  g_wh[2][(size_t)G_ * 512];
__device__ __nv_bfloat16  g_wl[2][(size_t)G_ * 512];

// ---------------------------------------------------------------------------
// Split-conversion (R8).
// ---------------------------------------------------------------------------
__global__ void conv_split(const float4* __restrict__ src,
                           __nv_bfloat162* __restrict__ hi,
                           __nv_bfloat162* __restrict__ lo, int n4)
{
    int i = blockIdx.x * blockDim.x + threadIdx.x;
    if (i >= n4) return;
    float4 v = src[i];
    __nv_bfloat16 h0 = __float2bfloat16(v.x), h1 = __float2bfloat16(v.y);
    __nv_bfloat16 h2 = __float2bfloat16(v.z), h3 = __float2bfloat16(v.w);
    hi[2 * i]     = __nv_bfloat162(h0, h1);
    hi[2 * i + 1] = __nv_bfloat162(h2, h3);
    lo[2 * i]     = __nv_bfloat162(__float2bfloat16(v.x - __bfloat162float(h0)),
                                   __float2bfloat16(v.y - __bfloat162float(h1)));
    lo[2 * i + 1] = __nv_bfloat162(__float2bfloat16(v.z - __bfloat162float(h2)),
                                   __float2bfloat16(v.w - __bfloat162float(h3)));
}

// ---------------------------------------------------------------------------
// Kernel 1: gi GEMM via HMMA (R8, unchanged).
// ---------------------------------------------------------------------------
#define PADB 40
#define ARRE (128 * PADB)
#define ARRB (ARRE * 2)
#define STGB (4 * ARRB)
#define GEMM_SMEM (2 * STGB)

__global__ void __launch_bounds__(256, 1) gi_gemm_tc(
    const float* __restrict__ bf, const float* __restrict__ br)
{
    extern __shared__ __nv_bfloat16 sm[];

    const int tid  = threadIdx.x;
    const int lane = tid & 31;
    const int warp = tid >> 5;
    const int dir  = blockIdx.z;
    const int n0   = blockIdx.x * 128;
    const int m0   = blockIdx.y * 128;

    const __nv_bfloat16* __restrict__ xh = g_xh;
    const __nv_bfloat16* __restrict__ xl = g_xl;
    const __nv_bfloat16* __restrict__ wh = g_wh[dir];
    const __nv_bfloat16* __restrict__ wl = g_wl[dir];
    const float* __restrict__ bias = dir ? br : bf;
    float* __restrict__ gi = g_gi[dir];

    const int r0 = tid >> 2;
    const int c8 = (tid & 3) * 8;
    const __nv_bfloat16* pxh = xh + (size_t)(m0 + r0) * 512 + c8;
    const __nv_bfloat16* pxl = xl + (size_t)(m0 + r0) * 512 + c8;
    const __nv_bfloat16* pwh = wh + (size_t)(n0 + r0) * 512 + c8;
    const __nv_bfloat16* pwl = wl + (size_t)(n0 + r0) * 512 + c8;
    const size_t rstep = (size_t)64 * 512;

    const int so0 = r0 * PADB + c8;
    const int so1 = (r0 + 64) * PADB + c8;

    const int wm = warp >> 2, wn = warp & 3;
    const int a_row = wm * 64 + (lane & 15);
    const int a_off = (a_row * PADB + (lane >> 4) * 8) * 2;
    const int b_row = wn * 32 + (lane & 7) + ((lane >> 4) << 3);
    const int b_off = (b_row * PADB + ((lane >> 3) & 1) * 8) * 2;

    const uint32_t smb = smem_u32(sm);

    float acc[4][4][4];
#pragma unroll
    for (int i = 0; i < 4; i++)
#pragma unroll
        for (int j = 0; j < 4; j++)
#pragma unroll
            for (int q = 0; q < 4; q++) acc[i][j][q] = 0.f;

    float4 vh0, vh1, vl0, vl1, uh0, uh1, ul0, ul1;
    vh0 = *(const float4*)(pxh); vh1 = *(const float4*)(pxh + rstep);
    vl0 = *(const float4*)(pxl); vl1 = *(const float4*)(pxl + rstep);
    uh0 = *(const float4*)(pwh); uh1 = *(const float4*)(pwh + rstep);
    ul0 = *(const float4*)(pwl); ul1 = *(const float4*)(pwl + rstep);
    *(float4*)&sm[0 * ARRE + so0] = vh0; *(float4*)&sm[0 * ARRE + so1] = vh1;
    *(float4*)&sm[1 * ARRE + so0] = vl0; *(float4*)&sm[1 * ARRE + so1] = vl1;
    *(float4*)&sm[2 * ARRE + so0] = uh0; *(float4*)&sm[2 * ARRE + so1] = uh1;
    *(float4*)&sm[3 * ARRE + so0] = ul0; *(float4*)&sm[3 * ARRE + so1] = ul1;
    __syncthreads();

    for (int c = 0; c < 16; c++) {
        const int st = c & 1;
        if (c < 15) {
            const int k0 = (c + 1) * 32;
            vh0 = *(const float4*)(pxh + k0); vh1 = *(const float4*)(pxh + k0 + rstep);
            vl0 = *(const float4*)(pxl + k0); vl1 = *(const float4*)(pxl + k0 + rstep);
            uh0 = *(const float4*)(pwh + k0); uh1 = *(const float4*)(pwh + k0 + rstep);
            ul0 = *(const float4*)(pwl + k0); ul1 = *(const float4*)(pwl + k0 + rstep);
        }

        const uint32_t sb = smb + st * STGB;
#pragma unroll
        for (int kk = 0; kk < 2; kk++) {
            const uint32_t kby = kk * 32;
            uint32_t ah[4][4], al[4][4], bh[2][4], bl[2][4];
#pragma unroll
            for (int mt = 0; mt < 4; mt++) {
                LDSM4(ah[mt], sb + 0 * ARRB + a_off + mt * (16 * PADB * 2) + kby);
                LDSM4(al[mt], sb + 1 * ARRB + a_off + mt * (16 * PADB * 2) + kby);
            }
#pragma unroll
            for (int np = 0; np < 2; np++) {
                LDSM4(bh[np], sb + 2 * ARRB + b_off + np * (16 * PADB * 2) + kby);
                LDSM4(bl[np], sb + 3 * ARRB + b_off + np * (16 * PADB * 2) + kby);
            }
#pragma unroll
            for (int mt = 0; mt < 4; mt++) {
#pragma unroll
                for (int nt = 0; nt < 4; nt++) {
                    const int np = nt >> 1, hf = (nt & 1) * 2;
                    MMA_BF16(acc[mt][nt], ah[mt], bh[np][hf], bh[np][hf + 1]);
                    MMA_BF16(acc[mt][nt], ah[mt], bl[np][hf], bl[np][hf + 1]);
                    MMA_BF16(acc[mt][nt], al[mt], bh[np][hf], bh[np][hf + 1]);
                }
            }
        }
        __syncthreads();
        if (c < 15) {
            const int os = (st ^ 1) * (STGB / 2);
            *(float4*)&sm[os + 0 * ARRE + so0] = vh0; *(float4*)&sm[os + 0 * ARRE + so1] = vh1;
            *(float4*)&sm[os + 1 * ARRE + so0] = vl0; *(float4*)&sm[os + 1 * ARRE + so1] = vl1;
            *(float4*)&sm[os + 2 * ARRE + so0] = uh0; *(float4*)&sm[os + 2 * ARRE + so1] = uh1;
            *(float4*)&sm[os + 3 * ARRE + so0] = ul0; *(float4*)&sm[os + 3 * ARRE + so1] = ul1;
            __syncthreads();
        }
    }

#pragma unroll
    for (int mt = 0; mt < 4; mt++) {
        const int m = m0 + wm * 64 + mt * 16 + (lane >> 2);
#pragma unroll
        for (int nt = 0; nt < 4; nt++) {
            const int n = n0 + wn * 32 + nt * 8 + (lane & 3) * 2;
            const float b0 = bias[n], b1 = bias[n + 1];
            *(float2*)&gi[(size_t)m * G_ + n] =
                make_float2(acc[mt][nt][0] + b0, acc[mt][nt][1] + b1);
            *(float2*)&gi[(size_t)(m + 8) * G_ + n] =
                make_float2(acc[mt][nt][2] + b0, acc[mt][nt][3] + b1);
        }
    }
}

// ---------------------------------------------------------------------------
// Kernel 2: recurrence with HMMA GEMV.
// SMEM (bytes): wh 96x520 bf16 | wl 96x520 | hh 8x520 | hl 8x520 |
//               red 4x96x10 fp32
// ---------------------------------------------------------------------------
#define WST 520
#define HST 520
#define OFF_WL (96 * WST)                 // bf16 units
#define OFF_HH (2 * 96 * WST)             // 99840
#define OFF_HL (OFF_HH + 8 * HST)         // 104000
#define OFF_RED_B ((OFF_HL + 8 * HST) * 2)  // byte offset 216320
#define SMEM_REC (OFF_RED_B + 4 * 96 * 10 * 4)  // 231680 B

__global__ void __launch_bounds__(256, 1) gru_rec(
    const float* __restrict__ h0,
    const float* __restrict__ whh_f, const float* __restrict__ bhh_f,
    const float* __restrict__ whh_r, const float* __restrict__ bhh_r,
    float* __restrict__ out, int out_size)
{
    extern __shared__ __nv_bfloat16 smb16[];
    __nv_bfloat16* swh = smb16;
    __nv_bfloat16* swl = smb16 + OFF_WL;
    __nv_bfloat16* shh = smb16 + OFF_HH;
    __nv_bfloat16* shl = smb16 + OFF_HL;
    float* red = (float*)((char*)smb16 + OFF_RED_B);

    const int tid  = threadIdx.x;
    const int warp = tid >> 5;
    const int lane = tid & 31;
    const int bid = blockIdx.x;
    const int dir = bid >> 6;
    const int bg  = (bid >> 4) & 3;
    const int sl  = bid & 15;

    const float* __restrict__ whh = dir ? whh_r : whh_f;
    const float* __restrict__ bhh = dir ? bhh_r : bhh_f;
    const float* __restrict__ gi  = g_gi[dir];
    unsigned* flags = &g_flags[dir][bg][0];
    const unsigned base = ld_acquire(flags + sl * 8);

    // w_hh slice -> SMEM as bf16 hi/lo. local row r = gate*32 + il2.
    for (int idx = tid; idx < 96 * 512; idx += 256) {
        int r = idx >> 9, k = idx & 511;
        float v = whh[(size_t)((r >> 5) * 512 + sl * 32 + (r & 31)) * 512 + k];
        __nv_bfloat16 h = __float2bfloat16(v);
        swh[r * WST + k] = h;
        swl[r * WST + k] = __float2bfloat16(v - __bfloat162float(h));
    }

    // Epilogue mapping: b == warp, il == lane.
    const int il = lane;
    const int iglob = sl * 32 + il;
    const int bglob = bg * 8 + warp;

    float hold = h0[(size_t)(dir * B_ + bglob) * H_ + iglob];
    {   // publish split h(0)
        __nv_bfloat16 hh2 = __float2bfloat16(hold);
        __nv_bfloat16 hl2 = __float2bfloat16(hold - __bfloat162float(hh2));
        st_cg_u16(&g_hh[dir][bg][0][warp][iglob], __bfloat16_as_ushort(hh2));
        st_cg_u16(&g_hl[dir][bg][0][warp][iglob], __bfloat16_as_ushort(hl2));
    }

    const float bh_r = bhh[iglob];
    const float bh_z = bhh[512 + iglob];
    const float bh_n = bhh[1024 + iglob];

    __syncthreads();
    if (tid == 0) st_release(flags + sl * 8, base + 1);

    const bool write_states = (out_size > T_ * B_ * 2 * H_);

    // ldmatrix lane offsets (bytes).
    const uint32_t smb = smem_u32(smb16);
    const uint32_t a_off = smb + (((lane & 15) * WST + 64 * warp + (lane >> 4) * 8) << 1);
    const uint32_t b_off = smb + (OFF_HH + (lane & 7) * HST + 64 * warp + (lane >> 3) * 8) * 2;

    // consumer load mapping: b = lane>>2, seg = lane&3 (16 bf16 per seg).
    const int cb = lane >> 2, cs = lane & 3;
    const int goff = cb * 512 + 64 * warp + cs * 16;
    uint4* sdh = (uint4*)(shh + cb * HST + 64 * warp + cs * 16);
    uint4* sdl = (uint4*)(shl + cb * HST + 64 * warp + cs * 16);

    const int src_flag = (2 * warp + (lane & 1)) * 8;

    for (int s = 0; s < T_; s++) {
        const int xrow = dir ? (T_ - 1 - s) : s;

        // gi loads before the poll.
        const float* gp = gi + ((size_t)xrow * B_ + bglob) * G_ + iglob;
        const float gir = __ldcs(gp);
        const float giz = __ldcs(gp + 512);
        const float gin = __ldcs(gp + 1024);

        // Per-warp acquire of this chunk's two source slices.
        {
            const unsigned target = base + 1 + (unsigned)s;
            while (ld_acquire(flags + src_flag) < target) __nanosleep(40);
            __syncwarp();
        }

        // Load this warp's h chunk (hi+lo) into warp-exclusive SMEM columns.
        {
            const uint4* ph = (const uint4*)(&g_hh[dir][bg][s & 1][0][0] + goff);
            const uint4* pl = (const uint4*)(&g_hl[dir][bg][s & 1][0][0] + goff);
            uint4 v0 = __ldcg(ph), v1 = __ldcg(ph + 1);
            uint4 u0 = __ldcg(pl), u1 = __ldcg(pl + 1);
            sdh[0] = v0; sdh[1] = v1;
            sdl[0] = u0; sdl[1] = u1;
        }
        __syncwarp();

        // HMMA: acc[mt] (16m x 8n) over this warp's 64 k.
        float acc[6][4];
#pragma unroll
        for (int mt = 0; mt < 6; mt++)
#pragma unroll
            for (int q = 0; q < 4; q++) acc[mt][q] = 0.f;

#pragma unroll
        for (int kp = 0; kp < 2; kp++) {
            uint32_t bhf[4], blf[4];
            LDSM4(bhf, b_off + kp * 64);
            LDSM4(blf, b_off + kp * 64 + (8 * HST * 2) * 0 + (OFF_HL - OFF_HH) * 2);
#pragma unroll
            for (int half = 0; half < 2; half++) {
                const uint32_t koff = kp * 64 + half * 32;
#pragma unroll
                for (int mt = 0; mt < 6; mt++) {
                    uint32_t ah[4], al[4];
                    LDSM4(ah, a_off + mt * (16 * WST * 2) + koff);
                    LDSM4(al, a_off + mt * (16 * WST * 2) + koff + OFF_WL * 2);
                    MMA_BF16(acc[mt], ah, bhf[half * 2], bhf[half * 2 + 1]);
                    MMA_BF16(acc[mt], ah, blf[half * 2], blf[half * 2 + 1]);
                    MMA_BF16(acc[mt], al, bhf[half * 2], bhf[half * 2 + 1]);
                }
            }
        }

        // 2-stage reduction of C partials: red[q][96][10].
        float* rb = red + (warp & 3) * 960;
        if (warp < 4) {
#pragma unroll
            for (int mt = 0; mt < 6; mt++) {
                const int r = mt * 16 + (lane >> 2);
                const int c = 2 * (lane & 3);
                *(float2*)&rb[r * 10 + c]       = make_float2(acc[mt][0], acc[mt][1]);
                *(float2*)&rb[(r + 8) * 10 + c] = make_float2(acc[mt][2], acc[mt][3]);
            }
        }
        __syncthreads();
        if (warp >= 4) {
#pragma unroll
            for (int mt = 0; mt < 6; mt++) {
                const int r = mt * 16 + (lane >> 2);
                const int c = 2 * (lane & 3);
                float2 p0 = *(float2*)&rb[r * 10 + c];
                float2 p1 = *(float2*)&rb[(r + 8) * 10 + c];
                *(float2*)&rb[r * 10 + c] =
                    make_float2(p0.x + acc[mt][0], p0.y + acc[mt][1]);
                *(float2*)&rb[(r + 8) * 10 + c] =
                    make_float2(p1.x + acc[mt][2], p1.y + acc[mt][3]);
            }
        }
        __syncthreads();

        // Epilogue: gh[r][b] = sum of 4 k-quarter partials.
        float ghr = bh_r, ghz = bh_z, ghn = bh_n;
#pragma unroll
        for (int q = 0; q < 4; q++) {
            const float* e = red + q * 960;
            ghr += e[il * 10 + warp];
            ghz += e[(32 + il) * 10 + warp];
            ghn += e[(64 + il) * 10 + warp];
        }

        const float rg = 1.f / (1.f + __expf(-(gir + ghr)));
        const float zg = 1.f / (1.f + __expf(-(giz + ghz)));
        const float ng = tanhf(gin + rg * ghn);
        const float hn = (1.f - zg) * ng + zg * hold;
        hold = hn;

        // Publish split h(s+1).
        {
            __nv_bfloat16 hh2 = __float2bfloat16(hn);
            __nv_bfloat16 hl2 = __float2bfloat16(hn - __bfloat162float(hh2));
            st_cg_u16(&g_hh[dir][bg][(s + 1) & 1][warp][iglob], __bfloat16_as_ushort(hh2));
            st_cg_u16(&g_hl[dir][bg][(s + 1) & 1][warp][iglob], __bfloat16_as_ushort(hl2));
        }
        __syncthreads();
        if (tid == 0) st_release(flags + sl * 8, base + 2 + (unsigned)s);

        // Off critical path: output stores.
        out[((size_t)s * B_ + bglob) * (2 * H_) + dir * H_ + iglob] = hn;
        if (write_states && s == T_ - 1)
            out[(size_t)T_ * B_ * 2 * H_ + (size_t)(dir * B_ + bglob) * H_ + iglob] = hn;
    }
}

// ---------------------------------------------------------------------------
extern "C" void kernel_launch(void* const* d_in, const int* in_sizes, int n_in,
                              void* d_out, int out_size)
{
    const float* x    = (const float*)d_in[0];
    const float* h0   = (const float*)d_in[1];
    const float* wihf = (const float*)d_in[2];
    const float* bihf = (const float*)d_in[3];
    const float* whhf = (const float*)d_in[4];
    const float* bhhf = (const float*)d_in[5];
    const float* wihr = (const float*)d_in[6];
    const float* bihr = (const float*)d_in[7];
    const float* whhr = (const float*)d_in[8];
    const float* bhhr = (const float*)d_in[9];
    float* out = (float*)d_out;

    __nv_bfloat16 *xh_p, *xl_p, *wh_p, *wl_p;
    cudaGetSymbolAddress((void**)&xh_p, g_xh);
    cudaGetSymbolAddress((void**)&xl_p, g_xl);
    cudaGetSymbolAddress((void**)&wh_p, g_wh);
    cudaGetSymbolAddress((void**)&wl_p, g_wl);

    {
        int n4 = (T_ * B_ * 512) / 4;
        conv_split<<<(n4 + 255) / 256, 256>>>((const float4*)x,
            (__nv_bfloat162*)xh_p, (__nv_bfloat162*)xl_p, n4);
        int w4 = (G_ * 512) / 4;
        conv_split<<<(w4 + 255) / 256, 256>>>((const float4*)wihf,
            (__nv_bfloat162*)wh_p, (__nv_bfloat162*)wl_p, w4);
        conv_split<<<(w4 + 255) / 256, 256>>>((const float4*)wihr,
            (__nv_bfloat162*)(wh_p + (size_t)G_ * 512),
            (__nv_bfloat162*)(wl_p + (size_t)G_ * 512), w4);
    }

    cudaFuncSetAttribute(gi_gemm_tc, cudaFuncAttributeMaxDynamicSharedMemorySize, GEMM_SMEM);
    dim3 g1(G_ / 128, (T_ * B_) / 128, 2);
    gi_gemm_tc<<<g1, 256, GEMM_SMEM>>>(bihf, bihr);

    cudaFuncSetAttribute(gru_rec, cudaFuncAttributeMaxDynamicSharedMemorySize, SMEM_REC);
    gru_rec<<<128, 256, SMEM_REC>>>(h0, whhf, bhhf, whhr, bhhr, out, out_size);
}

// round 10
// speedup vs baseline: 3.1918x; 1.0321x over previous
#include <cuda_runtime.h>
#include <cuda_bf16.h>
#include <cstdint>

// ---------------------------------------------------------------------------
// GRU_2602750181500: bidirectional GRU, T=2048, B=32, F=H=512, fp32.
// R10: recurrence = R9's HMMA GEMV, but wh A-fragments are hoisted into
//      registers before the time loop (loop-invariant weights; 48->24
//      A-side LDSM.x4 per warp per step). wl correction stays in SMEM.
//      GEMM/conv identical to R8/R9.
// ---------------------------------------------------------------------------

#define T_ 2048
#define B_ 32
#define H_ 512
#define G_ 1536

typedef unsigned long long ull;

__device__ __forceinline__ void st_release(unsigned* p, unsigned v) {
    asm volatile("st.release.gpu.global.u32 [%0], %1;" :: "l"(p), "r"(v) : "memory");
}
__device__ __forceinline__ unsigned ld_acquire(const unsigned* p) {
    unsigned v;
    asm volatile("ld.acquire.gpu.global.u32 %0, [%1];" : "=r"(v) : "l"(p) : "memory");
    return v;
}
__device__ __forceinline__ uint32_t smem_u32(const void* p) {
    uint32_t a;
    asm("{ .reg .u64 t; cvta.to.shared.u64 t, %1; cvt.u32.u64 %0, t; }"
        : "=r"(a) : "l"(p));
    return a;
}
__device__ __forceinline__ void st_cg_u16(unsigned short* p, unsigned short v) {
    asm volatile("st.global.cg.u16 [%0], %1;" :: "l"(p), "h"(v) : "memory");
}

#define LDSM4(r, addr) \
    asm volatile("ldmatrix.sync.aligned.m8n8.x4.shared.b16 {%0,%1,%2,%3}, [%4];" \
        : "=r"((r)[0]), "=r"((r)[1]), "=r"((r)[2]), "=r"((r)[3]) : "r"(addr))

#define MMA_BF16(d, a, b0, b1) \
    asm volatile("mma.sync.aligned.m16n8k16.row.col.f32.bf16.bf16.f32 " \
        "{%0,%1,%2,%3}, {%4,%5,%6,%7}, {%8,%9}, {%0,%1,%2,%3};" \
        : "+f"((d)[0]), "+f"((d)[1]), "+f"((d)[2]), "+f"((d)[3]) \
        : "r"((a)[0]), "r"((a)[1]), "r"((a)[2]), "r"((a)[3]), "r"(b0), "r"(b1))

// Scratch (device globals: allocation-free rule).
__device__ float          g_gi[2][(size_t)T_ * B_ * G_];
__device__ unsigned short g_hh[2][4][2][8][512];
__device__ unsigned short g_hl[2][4][2][8][512];
__device__ unsigned       g_flags[2][4][16 * 8];
__device__ __nv_bfloat16  g_xh[(size_t)T_ * B_ * 512];
__device__ __nv_bfloat16  g_xl[(size_t)T_ * B_ * 512];
__device__ __nv_bfloat16  g_wh[2][(size_t)G_ * 512];
__device__ __nv_bfloat16  g_wl[2][(size_t)G_ * 512];

// ---------------------------------------------------------------------------
// Split-conversion.
// ---------------------------------------------------------------------------
__global__ void conv_split(const float4* __restrict__ src,
                           __nv_bfloat162* __restrict__ hi,
                           __nv_bfloat162* __restrict__ lo, int n4)
{
    int i = blockIdx.x * blockDim.x + threadIdx.x;
    if (i >= n4) return;
    float4 v = src[i];
    __nv_bfloat16 h0 = __float2bfloat16(v.x), h1 = __float2bfloat16(v.y);
    __nv_bfloat16 h2 = __float2bfloat16(v.z), h3 = __float2bfloat16(v.w);
    hi[2 * i]     = __nv_bfloat162(h0, h1);
    hi[2 * i + 1] = __nv_bfloat162(h2, h3);
    lo[2 * i]     = __nv_bfloat162(__float2bfloat16(v.x - __bfloat162float(h0)),
                                   __float2bfloat16(v.y - __bfloat162float(h1)));
    lo[2 * i + 1] = __nv_bfloat162(__float2bfloat16(v.z - __bfloat162float(h2)),
                                   __float2bfloat16(v.w - __bfloat162float(h3)));
}

// ---------------------------------------------------------------------------
// Kernel 1: gi GEMM via HMMA (unchanged).
// ---------------------------------------------------------------------------
#define PADB 40
#define ARRE (128 * PADB)
#define ARRB (ARRE * 2)
#define STGB (4 * ARRB)
#define GEMM_SMEM (2 * STGB)

__global__ void __launch_bounds__(256, 1) gi_gemm_tc(
    const float* __restrict__ bf, const float* __restrict__ br)
{
    extern __shared__ __nv_bfloat16 sm[];

    const int tid  = threadIdx.x;
    const int lane = tid & 31;
    const int warp = tid >> 5;
    const int dir  = blockIdx.z;
    const int n0   = blockIdx.x * 128;
    const int m0   = blockIdx.y * 128;

    const __nv_bfloat16* __restrict__ xh = g_xh;
    const __nv_bfloat16* __restrict__ xl = g_xl;
    const __nv_bfloat16* __restrict__ wh = g_wh[dir];
    const __nv_bfloat16* __restrict__ wl = g_wl[dir];
    const float* __restrict__ bias = dir ? br : bf;
    float* __restrict__ gi = g_gi[dir];

    const int r0 = tid >> 2;
    const int c8 = (tid & 3) * 8;
    const __nv_bfloat16* pxh = xh + (size_t)(m0 + r0) * 512 + c8;
    const __nv_bfloat16* pxl = xl + (size_t)(m0 + r0) * 512 + c8;
    const __nv_bfloat16* pwh = wh + (size_t)(n0 + r0) * 512 + c8;
    const __nv_bfloat16* pwl = wl + (size_t)(n0 + r0) * 512 + c8;
    const size_t rstep = (size_t)64 * 512;

    const int so0 = r0 * PADB + c8;
    const int so1 = (r0 + 64) * PADB + c8;

    const int wm = warp >> 2, wn = warp & 3;
    const int a_row = wm * 64 + (lane & 15);
    const int a_off = (a_row * PADB + (lane >> 4) * 8) * 2;
    const int b_row = wn * 32 + (lane & 7) + ((lane >> 4) << 3);
    const int b_off = (b_row * PADB + ((lane >> 3) & 1) * 8) * 2;

    const uint32_t smb = smem_u32(sm);

    float acc[4][4][4];
#pragma unroll
    for (int i = 0; i < 4; i++)
#pragma unroll
        for (int j = 0; j < 4; j++)
#pragma unroll
            for (int q = 0; q < 4; q++) acc[i][j][q] = 0.f;

    float4 vh0, vh1, vl0, vl1, uh0, uh1, ul0, ul1;
    vh0 = *(const float4*)(pxh); vh1 = *(const float4*)(pxh + rstep);
    vl0 = *(const float4*)(pxl); vl1 = *(const float4*)(pxl + rstep);
    uh0 = *(const float4*)(pwh); uh1 = *(const float4*)(pwh + rstep);
    ul0 = *(const float4*)(pwl); ul1 = *(const float4*)(pwl + rstep);
    *(float4*)&sm[0 * ARRE + so0] = vh0; *(float4*)&sm[0 * ARRE + so1] = vh1;
    *(float4*)&sm[1 * ARRE + so0] = vl0; *(float4*)&sm[1 * ARRE + so1] = vl1;
    *(float4*)&sm[2 * ARRE + so0] = uh0; *(float4*)&sm[2 * ARRE + so1] = uh1;
    *(float4*)&sm[3 * ARRE + so0] = ul0; *(float4*)&sm[3 * ARRE + so1] = ul1;
    __syncthreads();

    for (int c = 0; c < 16; c++) {
        const int st = c & 1;
        if (c < 15) {
            const int k0 = (c + 1) * 32;
            vh0 = *(const float4*)(pxh + k0); vh1 = *(const float4*)(pxh + k0 + rstep);
            vl0 = *(const float4*)(pxl + k0); vl1 = *(const float4*)(pxl + k0 + rstep);
            uh0 = *(const float4*)(pwh + k0); uh1 = *(const float4*)(pwh + k0 + rstep);
            ul0 = *(const float4*)(pwl + k0); ul1 = *(const float4*)(pwl + k0 + rstep);
        }

        const uint32_t sb = smb + st * STGB;
#pragma unroll
        for (int kk = 0; kk < 2; kk++) {
            const uint32_t kby = kk * 32;
            uint32_t ah[4][4], al[4][4], bh[2][4], bl[2][4];
#pragma unroll
            for (int mt = 0; mt < 4; mt++) {
                LDSM4(ah[mt], sb + 0 * ARRB + a_off + mt * (16 * PADB * 2) + kby);
                LDSM4(al[mt], sb + 1 * ARRB + a_off + mt * (16 * PADB * 2) + kby);
            }
#pragma unroll
            for (int np = 0; np < 2; np++) {
                LDSM4(bh[np], sb + 2 * ARRB + b_off + np * (16 * PADB * 2) + kby);
                LDSM4(bl[np], sb + 3 * ARRB + b_off + np * (16 * PADB * 2) + kby);
            }
#pragma unroll
            for (int mt = 0; mt < 4; mt++) {
#pragma unroll
                for (int nt = 0; nt < 4; nt++) {
                    const int np = nt >> 1, hf = (nt & 1) * 2;
                    MMA_BF16(acc[mt][nt], ah[mt], bh[np][hf], bh[np][hf + 1]);
                    MMA_BF16(acc[mt][nt], ah[mt], bl[np][hf], bl[np][hf + 1]);
                    MMA_BF16(acc[mt][nt], al[mt], bh[np][hf], bh[np][hf + 1]);
                }
            }
        }
        __syncthreads();
        if (c < 15) {
            const int os = (st ^ 1) * (STGB / 2);
            *(float4*)&sm[os + 0 * ARRE + so0] = vh0; *(float4*)&sm[os + 0 * ARRE + so1] = vh1;
            *(float4*)&sm[os + 1 * ARRE + so0] = vl0; *(float4*)&sm[os + 1 * ARRE + so1] = vl1;
            *(float4*)&sm[os + 2 * ARRE + so0] = uh0; *(float4*)&sm[os + 2 * ARRE + so1] = uh1;
            *(float4*)&sm[os + 3 * ARRE + so0] = ul0; *(float4*)&sm[os + 3 * ARRE + so1] = ul1;
            __syncthreads();
        }
    }

#pragma unroll
    for (int mt = 0; mt < 4; mt++) {
        const int m = m0 + wm * 64 + mt * 16 + (lane >> 2);
#pragma unroll
        for (int nt = 0; nt < 4; nt++) {
            const int n = n0 + wn * 32 + nt * 8 + (lane & 3) * 2;
            const float b0 = bias[n], b1 = bias[n + 1];
            *(float2*)&gi[(size_t)m * G_ + n] =
                make_float2(acc[mt][nt][0] + b0, acc[mt][nt][1] + b1);
            *(float2*)&gi[(size_t)(m + 8) * G_ + n] =
                make_float2(acc[mt][nt][2] + b0, acc[mt][nt][3] + b1);
        }
    }
}

// ---------------------------------------------------------------------------
// Kernel 2: recurrence, HMMA GEMV with register-resident wh fragments.
// ---------------------------------------------------------------------------
#define WST 520
#define HST 520
#define OFF_WL (96 * WST)
#define OFF_HH (2 * 96 * WST)
#define OFF_HL (OFF_HH + 8 * HST)
#define OFF_RED_B ((OFF_HL + 8 * HST) * 2)
#define SMEM_REC (OFF_RED_B + 4 * 96 * 10 * 4)

__global__ void __launch_bounds__(256, 1) gru_rec(
    const float* __restrict__ h0,
    const float* __restrict__ whh_f, const float* __restrict__ bhh_f,
    const float* __restrict__ whh_r, const float* __restrict__ bhh_r,
    float* __restrict__ out, int out_size)
{
    extern __shared__ __nv_bfloat16 smb16[];
    __nv_bfloat16* swh = smb16;
    __nv_bfloat16* swl = smb16 + OFF_WL;
    __nv_bfloat16* shh = smb16 + OFF_HH;
    __nv_bfloat16* shl = smb16 + OFF_HL;
    float* red = (float*)((char*)smb16 + OFF_RED_B);

    const int tid  = threadIdx.x;
    const int warp = tid >> 5;
    const int lane = tid & 31;
    const int bid = blockIdx.x;
    const int dir = bid >> 6;
    const int bg  = (bid >> 4) & 3;
    const int sl  = bid & 15;

    const float* __restrict__ whh = dir ? whh_r : whh_f;
    const float* __restrict__ bhh = dir ? bhh_r : bhh_f;
    const float* __restrict__ gi  = g_gi[dir];
    unsigned* flags = &g_flags[dir][bg][0];
    const unsigned base = ld_acquire(flags + sl * 8);

    // w_hh slice -> SMEM as bf16 hi/lo.
    for (int idx = tid; idx < 96 * 512; idx += 256) {
        int r = idx >> 9, k = idx & 511;
        float v = whh[(size_t)((r >> 5) * 512 + sl * 32 + (r & 31)) * 512 + k];
        __nv_bfloat16 h = __float2bfloat16(v);
        swh[r * WST + k] = h;
        swl[r * WST + k] = __float2bfloat16(v - __bfloat162float(h));
    }

    const int il = lane;
    const int iglob = sl * 32 + il;
    const int bglob = bg * 8 + warp;

    float hold = h0[(size_t)(dir * B_ + bglob) * H_ + iglob];
    {
        __nv_bfloat16 hh2 = __float2bfloat16(hold);
        __nv_bfloat16 hl2 = __float2bfloat16(hold - __bfloat162float(hh2));
        st_cg_u16(&g_hh[dir][bg][0][warp][iglob], __bfloat16_as_ushort(hh2));
        st_cg_u16(&g_hl[dir][bg][0][warp][iglob], __bfloat16_as_ushort(hl2));
    }

    const float bh_r = bhh[iglob];
    const float bh_z = bhh[512 + iglob];
    const float bh_n = bhh[1024 + iglob];

    __syncthreads();

    // ldmatrix lane offsets (bytes).
    const uint32_t smb = smem_u32(smb16);
    const uint32_t a_off = smb + (((lane & 15) * WST + 64 * warp + (lane >> 4) * 8) << 1);
    const uint32_t b_off = smb + (OFF_HH + (lane & 7) * HST + 64 * warp + (lane >> 3) * 8) * 2;

    // Hoist wh A-fragments into registers (loop-invariant across 2048 steps).
    uint32_t awh[6][4][4];
#pragma unroll
    for (int mt = 0; mt < 6; mt++)
#pragma unroll
        for (int k16 = 0; k16 < 4; k16++)
            LDSM4(awh[mt][k16], a_off + mt * (16 * WST * 2) + k16 * 32);

    if (tid == 0) st_release(flags + sl * 8, base + 1);

    const bool write_states = (out_size > T_ * B_ * 2 * H_);

    // consumer load mapping: b = lane>>2, seg = lane&3 (16 bf16 per seg).
    const int cb = lane >> 2, cs = lane & 3;
    const int goff = cb * 512 + 64 * warp + cs * 16;
    uint4* sdh = (uint4*)(shh + cb * HST + 64 * warp + cs * 16);
    uint4* sdl = (uint4*)(shl + cb * HST + 64 * warp + cs * 16);

    const int src_flag = (2 * warp + (lane & 1)) * 8;

    for (int s = 0; s < T_; s++) {
        const int xrow = dir ? (T_ - 1 - s) : s;

        const float* gp = gi + ((size_t)xrow * B_ + bglob) * G_ + iglob;
        const float gir = __ldcs(gp);
        const float giz = __ldcs(gp + 512);
        const float gin = __ldcs(gp + 1024);

        {
            const unsigned target = base + 1 + (unsigned)s;
            while (ld_acquire(flags + src_flag) < target) __nanosleep(40);
            __syncwarp();
        }

        {
            const uint4* ph = (const uint4*)(&g_hh[dir][bg][s & 1][0][0] + goff);
            const uint4* pl = (const uint4*)(&g_hl[dir][bg][s & 1][0][0] + goff);
            uint4 v0 = __ldcg(ph), v1 = __ldcg(ph + 1);
            uint4 u0 = __ldcg(pl), u1 = __ldcg(pl + 1);
            sdh[0] = v0; sdh[1] = v1;
            sdl[0] = u0; sdl[1] = u1;
        }
        __syncwarp();

        float acc[6][4];
#pragma unroll
        for (int mt = 0; mt < 6; mt++)
#pragma unroll
            for (int q = 0; q < 4; q++) acc[mt][q] = 0.f;

#pragma unroll
        for (int kp = 0; kp < 2; kp++) {
            uint32_t bhf[4], blf[4];
            LDSM4(bhf, b_off + kp * 64);
            LDSM4(blf, b_off + kp * 64 + (OFF_HL - OFF_HH) * 2);
#pragma unroll
            for (int half = 0; half < 2; half++) {
                const int k16 = kp * 2 + half;
                const uint32_t koff = k16 * 32;
#pragma unroll
                for (int mt = 0; mt < 6; mt++) {
                    uint32_t al[4];
                    LDSM4(al, a_off + mt * (16 * WST * 2) + koff + OFF_WL * 2);
                    MMA_BF16(acc[mt], awh[mt][k16], bhf[half * 2], bhf[half * 2 + 1]);
                    MMA_BF16(acc[mt], awh[mt][k16], blf[half * 2], blf[half * 2 + 1]);
                    MMA_BF16(acc[mt], al, bhf[half * 2], bhf[half * 2 + 1]);
                }
            }
        }

        // 2-stage reduction of C partials: red[q][96][10].
        float* rb = red + (warp & 3) * 960;
        if (warp < 4) {
#pragma unroll
            for (int mt = 0; mt < 6; mt++) {
                const int r = mt * 16 + (lane >> 2);
                const int c = 2 * (lane & 3);
                *(float2*)&rb[r * 10 + c]       = make_float2(acc[mt][0], acc[mt][1]);
                *(float2*)&rb[(r + 8) * 10 + c] = make_float2(acc[mt][2], acc[mt][3]);
            }
        }
        __syncthreads();
        if (warp >= 4) {
#pragma unroll
            for (int mt = 0; mt < 6; mt++) {
                const int r = mt * 16 + (lane >> 2);
                const int c = 2 * (lane & 3);
                float2 p0 = *(float2*)&rb[r * 10 + c];
                float2 p1 = *(float2*)&rb[(r + 8) * 10 + c];
                *(float2*)&rb[r * 10 + c] =
                    make_float2(p0.x + acc[mt][0], p0.y + acc[mt][1]);
                *(float2*)&rb[(r + 8) * 10 + c] =
                    make_float2(p1.x + acc[mt][2], p1.y + acc[mt][3]);
            }
        }
        __syncthreads();

        float ghr = bh_r, ghz = bh_z, ghn = bh_n;
#pragma unroll
        for (int q = 0; q < 4; q++) {
            const float* e = red + q * 960;
            ghr += e[il * 10 + warp];
            ghz += e[(32 + il) * 10 + warp];
            ghn += e[(64 + il) * 10 + warp];
        }

        const float rg = 1.f / (1.f + __expf(-(gir + ghr)));
        const float zg = 1.f / (1.f + __expf(-(giz + ghz)));
        const float ng = tanhf(gin + rg * ghn);
        const float hn = (1.f - zg) * ng + zg * hold;
        hold = hn;

        {
            __nv_bfloat16 hh2 = __float2bfloat16(hn);
            __nv_bfloat16 hl2 = __float2bfloat16(hn - __bfloat162float(hh2));
            st_cg_u16(&g_hh[dir][bg][(s + 1) & 1][warp][iglob], __bfloat16_as_ushort(hh2));
            st_cg_u16(&g_hl[dir][bg][(s + 1) & 1][warp][iglob], __bfloat16_as_ushort(hl2));
        }
        __syncthreads();
        if (tid == 0) st_release(flags + sl * 8, base + 2 + (unsigned)s);

        out[((size_t)s * B_ + bglob) * (2 * H_) + dir * H_ + iglob] = hn;
        if (write_states && s == T_ - 1)
            out[(size_t)T_ * B_ * 2 * H_ + (size_t)(dir * B_ + bglob) * H_ + iglob] = hn;
    }
}

// ---------------------------------------------------------------------------
extern "C" void kernel_launch(void* const* d_in, const int* in_sizes, int n_in,
                              void* d_out, int out_size)
{
    const float* x    = (const float*)d_in[0];
    const float* h0   = (const float*)d_in[1];
    const float* wihf = (const float*)d_in[2];
    const float* bihf = (const float*)d_in[3];
    const float* whhf = (const float*)d_in[4];
    const float* bhhf = (const float*)d_in[5];
    const float* wihr = (const float*)d_in[6];
    const float* bihr = (const float*)d_in[7];
    const float* whhr = (const float*)d_in[8];
    const float* bhhr = (const float*)d_in[9];
    float* out = (float*)d_out;

    __nv_bfloat16 *xh_p, *xl_p, *wh_p, *wl_p;
    cudaGetSymbolAddress((void**)&xh_p, g_xh);
    cudaGetSymbolAddress((void**)&xl_p, g_xl);
    cudaGetSymbolAddress((void**)&wh_p, g_wh);
    cudaGetSymbolAddress((void**)&wl_p, g_wl);

    {
        int n4 = (T_ * B_ * 512) / 4;
        conv_split<<<(n4 + 255) / 256, 256>>>((const float4*)x,
            (__nv_bfloat162*)xh_p, (__nv_bfloat162*)xl_p, n4);
        int w4 = (G_ * 512) / 4;
        conv_split<<<(w4 + 255) / 256, 256>>>((const float4*)wihf,
            (__nv_bfloat162*)wh_p, (__nv_bfloat162*)wl_p, w4);
        conv_split<<<(w4 + 255) / 256, 256>>>((const float4*)wihr,
            (__nv_bfloat162*)(wh_p + (size_t)G_ * 512),
            (__nv_bfloat162*)(wl_p + (size_t)G_ * 512), w4);
    }

    cudaFuncSetAttribute(gi_gemm_tc, cudaFuncAttributeMaxDynamicSharedMemorySize, GEMM_SMEM);
    dim3 g1(G_ / 128, (T_ * B_) / 128, 2);
    gi_gemm_tc<<<g1, 256, GEMM_SMEM>>>(bihf, bihr);

    cudaFuncSetAttribute(gru_rec, cudaFuncAttributeMaxDynamicSharedMemorySize, SMEM_REC);
    gru_rec<<<128, 256, SMEM_REC>>>(h0, whhf, bhhf, whhr, bhhr, out, out_size);
}